// round 1
// baseline (speedup 1.0000x reference)
#include <cuda_runtime.h>
#include <math.h>

#define BB 4
#define NN 2048
#define MM 2048
#define QD 512
#define CD 64
#define NH 8
#define HD 64
#define INNER 512
#define GATE_HID 32

// Scratch (allocation-free rule: __device__ globals)
__device__ float g_gctx[BB * MM * CD];        //  2 MB gated context
__device__ float g_Q[BB * NN * INNER];        // 16 MB
__device__ float g_K[BB * MM * INNER];        // 16 MB
__device__ float g_V[BB * MM * INNER];        // 16 MB
__device__ float g_A[BB * NN * INNER];        // 16 MB attention output (pre-Wo)

// ---------------------------------------------------------------------------
// Kernel 1: gate = sigmoid(relu(ctx @ W1 + b1) @ W2 + b2); gctx = ctx * gate
// One warp per context row. 8 rows per 256-thread block.
// ---------------------------------------------------------------------------
__global__ __launch_bounds__(256) void gate_kernel(
    const float* __restrict__ ctx, const float* __restrict__ W1,
    const float* __restrict__ b1, const float* __restrict__ W2,
    const float* __restrict__ b2, float* __restrict__ gctx) {
    __shared__ float W1s[CD * GATE_HID];
    __shared__ float W2s[GATE_HID];
    __shared__ float b1s[GATE_HID];
    __shared__ float cs[8][CD];

    const int tid = threadIdx.x;
    for (int i = tid; i < CD * GATE_HID; i += 256) W1s[i] = W1[i];
    if (tid < GATE_HID) { W2s[tid] = W2[tid]; b1s[tid] = b1[tid]; }
    __syncthreads();

    const int warp = tid >> 5, lane = tid & 31;
    const int row = blockIdx.x * 8 + warp;  // [0, BB*MM)
    const float* c = ctx + (size_t)row * CD;
    cs[warp][lane]      = c[lane];
    cs[warp][lane + 32] = c[lane + 32];
    __syncwarp();

    // lane j computes hidden unit j (GATE_HID == 32 == warp size)
    float h = b1s[lane];
#pragma unroll
    for (int i = 0; i < CD; i++) h = fmaf(cs[warp][i], W1s[i * GATE_HID + lane], h);
    h = fmaxf(h, 0.0f);
    float part = h * W2s[lane];
#pragma unroll
    for (int off = 16; off; off >>= 1) part += __shfl_xor_sync(0xffffffffu, part, off);
    const float g = 1.0f / (1.0f + __expf(-(part + b2[0])));

    float* dst = gctx + (size_t)row * CD;
    dst[lane]      = cs[warp][lane] * g;
    dst[lane + 32] = cs[warp][lane + 32] * g;
}

// ---------------------------------------------------------------------------
// Kernel 2: fp32 SGEMM  C[M,N] = A[M,K] @ B[K,N] (+ bias)
// 128x128 block tile, BK=8, 256 threads, 8x8 register tile per thread
// (split as 2x(4) rows x 2x(4) cols for vectorized shared loads).
// Requires M%128==0, N%128==0, K%8==0.
// ---------------------------------------------------------------------------
template <bool BIAS>
__global__ __launch_bounds__(256) void sgemm_kernel(
    const float* __restrict__ A, const float* __restrict__ Bm,
    const float* __restrict__ bias, float* __restrict__ C,
    int M, int N, int K) {
    __shared__ float As[8][128];  // transposed A tile: As[k][m]
    __shared__ float Bs[8][128];  // Bs[k][n]

    const int bm = blockIdx.y * 128;
    const int bn = blockIdx.x * 128;
    const int tid = threadIdx.x;

    // A tile: 128 rows x 8 cols; thread loads float4: row=tid/2, col=(tid&1)*4
    const int arow = tid >> 1, acol = (tid & 1) * 4;
    // B tile: 8 rows x 128 cols; thread loads float4: row=tid/32, col=(tid&31)*4
    const int brow = tid >> 5, bcol = (tid & 31) * 4;

    const int tx = tid & 15;   // 16 col-groups
    const int ty = tid >> 4;   // 16 row-groups

    float acc[8][8];
#pragma unroll
    for (int i = 0; i < 8; i++)
#pragma unroll
        for (int j = 0; j < 8; j++) acc[i][j] = 0.0f;

    for (int k0 = 0; k0 < K; k0 += 8) {
        float4 av = *(const float4*)&A[(size_t)(bm + arow) * K + k0 + acol];
        float4 bv = *(const float4*)&Bm[(size_t)(k0 + brow) * N + bn + bcol];
        As[acol + 0][arow] = av.x;
        As[acol + 1][arow] = av.y;
        As[acol + 2][arow] = av.z;
        As[acol + 3][arow] = av.w;
        *(float4*)&Bs[brow][bcol] = bv;
        __syncthreads();

#pragma unroll
        for (int k = 0; k < 8; k++) {
            float a[8], b[8];
            float4 a0 = *(const float4*)&As[k][ty * 4];
            float4 a1 = *(const float4*)&As[k][64 + ty * 4];
            float4 b0 = *(const float4*)&Bs[k][tx * 4];
            float4 b1 = *(const float4*)&Bs[k][64 + tx * 4];
            a[0] = a0.x; a[1] = a0.y; a[2] = a0.z; a[3] = a0.w;
            a[4] = a1.x; a[5] = a1.y; a[6] = a1.z; a[7] = a1.w;
            b[0] = b0.x; b[1] = b0.y; b[2] = b0.z; b[3] = b0.w;
            b[4] = b1.x; b[5] = b1.y; b[6] = b1.z; b[7] = b1.w;
#pragma unroll
            for (int i = 0; i < 8; i++)
#pragma unroll
                for (int j = 0; j < 8; j++) acc[i][j] = fmaf(a[i], b[j], acc[i][j]);
        }
        __syncthreads();
    }

#pragma unroll
    for (int ih = 0; ih < 2; ih++) {
#pragma unroll
        for (int i = 0; i < 4; i++) {
            const int r = bm + ih * 64 + ty * 4 + i;
            float* crow = C + (size_t)r * N + bn;
#pragma unroll
            for (int jh = 0; jh < 2; jh++) {
                const int cbase = jh * 64 + tx * 4;
                float4 v = make_float4(acc[ih * 4 + i][jh * 4 + 0],
                                       acc[ih * 4 + i][jh * 4 + 1],
                                       acc[ih * 4 + i][jh * 4 + 2],
                                       acc[ih * 4 + i][jh * 4 + 3]);
                if (BIAS) {
                    v.x += bias[bn + cbase + 0];
                    v.y += bias[bn + cbase + 1];
                    v.z += bias[bn + cbase + 2];
                    v.w += bias[bn + cbase + 3];
                }
                *(float4*)&crow[cbase] = v;
            }
        }
    }
}

// ---------------------------------------------------------------------------
// Kernel 3: flash attention, fp32, online softmax.
// grid (NN/64, NH, BB), 256 threads. 64 query rows x 64-key tiles, D=64.
// Each row handled by 4 lanes (16 cols each). Score tile -> shared (reusing
// the K buffer) -> P@V accumulate.
// ---------------------------------------------------------------------------
#define SKP 68  // padded stride for Kt / P union buffer (16B-aligned rows)

__global__ __launch_bounds__(256) void flash_kernel(
    const float* __restrict__ Q, const float* __restrict__ K,
    const float* __restrict__ V, float* __restrict__ O) {
    extern __shared__ float sh[];
    float* Qst = sh;                       // [64][64]  Qst[k][r]
    float* KP  = sh + 64 * 64;             // [64][SKP] Kt[k][c] then P[r][j]
    float* Vs  = sh + 64 * 64 + 64 * SKP;  // [64][64]  Vs[j][d]

    const int b = blockIdx.z, h = blockIdx.y;
    const int q0 = blockIdx.x * 64;
    const int tid = threadIdx.x;
    const int lane = tid & 31;
    const int r  = (tid >> 5) * 8 + (lane >> 2);  // query row 0..63
    const int cg = (lane & 3) * 16;               // 16-wide column chunk
    const int lr = tid >> 2;                      // loader row 0..63
    const int lc = (tid & 3) * 16;                // loader col chunk

    const float* Qb = Q + ((size_t)b * NN + q0) * INNER + h * HD;
    const float* Kb = K + (size_t)b * MM * INNER + h * HD;
    const float* Vb = V + (size_t)b * MM * INNER + h * HD;

    // Load Q tile transposed, pre-scaled by 1/sqrt(D)=0.125
    {
        const float* src = Qb + (size_t)lr * INNER + lc;
#pragma unroll
        for (int j = 0; j < 16; j += 4) {
            float4 v = *(const float4*)(src + j);
            Qst[(lc + j + 0) * 64 + lr] = v.x * 0.125f;
            Qst[(lc + j + 1) * 64 + lr] = v.y * 0.125f;
            Qst[(lc + j + 2) * 64 + lr] = v.z * 0.125f;
            Qst[(lc + j + 3) * 64 + lr] = v.w * 0.125f;
        }
    }

    float o[16];
#pragma unroll
    for (int j = 0; j < 16; j++) o[j] = 0.0f;
    float m = -1e30f, l = 0.0f;
    __syncthreads();

    for (int t = 0; t < MM; t += 64) {
        // Load K tile transposed (Kt[k][c]) and V tile direct (Vs[j][d])
        const float* ksrc = Kb + (size_t)(t + lr) * INNER + lc;
#pragma unroll
        for (int j = 0; j < 16; j += 4) {
            float4 v = *(const float4*)(ksrc + j);
            KP[(lc + j + 0) * SKP + lr] = v.x;
            KP[(lc + j + 1) * SKP + lr] = v.y;
            KP[(lc + j + 2) * SKP + lr] = v.z;
            KP[(lc + j + 3) * SKP + lr] = v.w;
        }
        const float* vsrc = Vb + (size_t)(t + lr) * INNER + lc;
#pragma unroll
        for (int j = 0; j < 16; j += 4)
            *(float4*)&Vs[lr * 64 + lc + j] = *(const float4*)(vsrc + j);
        __syncthreads();

        // Scores: s[j] = sum_k Qst[k][r] * Kt[k][cg+j]
        float s[16];
#pragma unroll
        for (int j = 0; j < 16; j++) s[j] = 0.0f;
#pragma unroll 4
        for (int k = 0; k < 64; k++) {
            const float qv = Qst[k * 64 + r];
            const float4* kp = (const float4*)&KP[k * SKP + cg];
            float4 a0 = kp[0], a1 = kp[1], a2 = kp[2], a3 = kp[3];
            s[0]  = fmaf(qv, a0.x, s[0]);  s[1]  = fmaf(qv, a0.y, s[1]);
            s[2]  = fmaf(qv, a0.z, s[2]);  s[3]  = fmaf(qv, a0.w, s[3]);
            s[4]  = fmaf(qv, a1.x, s[4]);  s[5]  = fmaf(qv, a1.y, s[5]);
            s[6]  = fmaf(qv, a1.z, s[6]);  s[7]  = fmaf(qv, a1.w, s[7]);
            s[8]  = fmaf(qv, a2.x, s[8]);  s[9]  = fmaf(qv, a2.y, s[9]);
            s[10] = fmaf(qv, a2.z, s[10]); s[11] = fmaf(qv, a2.w, s[11]);
            s[12] = fmaf(qv, a3.x, s[12]); s[13] = fmaf(qv, a3.y, s[13]);
            s[14] = fmaf(qv, a3.z, s[14]); s[15] = fmaf(qv, a3.w, s[15]);
        }

        // Online softmax (row stats across the 4 lanes of this row)
        float mt = s[0];
#pragma unroll
        for (int j = 1; j < 16; j++) mt = fmaxf(mt, s[j]);
        mt = fmaxf(mt, __shfl_xor_sync(0xffffffffu, mt, 1));
        mt = fmaxf(mt, __shfl_xor_sync(0xffffffffu, mt, 2));
        const float mnew = fmaxf(m, mt);
        const float alpha = __expf(m - mnew);
        float ls = 0.0f;
#pragma unroll
        for (int j = 0; j < 16; j++) { s[j] = __expf(s[j] - mnew); ls += s[j]; }
        ls += __shfl_xor_sync(0xffffffffu, ls, 1);
        ls += __shfl_xor_sync(0xffffffffu, ls, 2);
        l = l * alpha + ls;
        m = mnew;
#pragma unroll
        for (int j = 0; j < 16; j++) o[j] *= alpha;

        __syncthreads();  // all score reads of Kt done before P overwrite
#pragma unroll
        for (int j = 0; j < 16; j += 4)
            *(float4*)&KP[r * SKP + cg + j] =
                make_float4(s[j], s[j + 1], s[j + 2], s[j + 3]);
        __syncthreads();

        // o[d] += sum_j P[r][j] * Vs[j][d]
#pragma unroll 4
        for (int k = 0; k < 64; k++) {
            const float p = KP[r * SKP + k];
            const float4* vp = (const float4*)&Vs[k * 64 + cg];
            float4 v0 = vp[0], v1 = vp[1], v2 = vp[2], v3 = vp[3];
            o[0]  = fmaf(p, v0.x, o[0]);  o[1]  = fmaf(p, v0.y, o[1]);
            o[2]  = fmaf(p, v0.z, o[2]);  o[3]  = fmaf(p, v0.w, o[3]);
            o[4]  = fmaf(p, v1.x, o[4]);  o[5]  = fmaf(p, v1.y, o[5]);
            o[6]  = fmaf(p, v1.z, o[6]);  o[7]  = fmaf(p, v1.w, o[7]);
            o[8]  = fmaf(p, v2.x, o[8]);  o[9]  = fmaf(p, v2.y, o[9]);
            o[10] = fmaf(p, v2.z, o[10]); o[11] = fmaf(p, v2.w, o[11]);
            o[12] = fmaf(p, v3.x, o[12]); o[13] = fmaf(p, v3.y, o[13]);
            o[14] = fmaf(p, v3.z, o[14]); o[15] = fmaf(p, v3.w, o[15]);
        }
        __syncthreads();  // before next tile overwrites KP/Vs
    }

    const float inv = 1.0f / l;
    float* dst = O + ((size_t)b * NN + q0 + r) * INNER + h * HD + cg;
#pragma unroll
    for (int j = 0; j < 16; j += 4)
        *(float4*)(dst + j) = make_float4(o[j] * inv, o[j + 1] * inv,
                                          o[j + 2] * inv, o[j + 3] * inv);
}

// ---------------------------------------------------------------------------
extern "C" void kernel_launch(void* const* d_in, const int* in_sizes, int n_in,
                              void* d_out, int out_size) {
    const float* x   = (const float*)d_in[0];
    const float* ctx = (const float*)d_in[1];
    const float* Wq  = (const float*)d_in[2];
    const float* Wk  = (const float*)d_in[3];
    const float* Wv  = (const float*)d_in[4];
    const float* W1  = (const float*)d_in[5];
    const float* b1  = (const float*)d_in[6];
    const float* W2  = (const float*)d_in[7];
    const float* b2  = (const float*)d_in[8];
    const float* Wo  = (const float*)d_in[9];
    const float* bo  = (const float*)d_in[10];
    float* out = (float*)d_out;

    float *gctx, *Qp, *Kp, *Vp, *Ap;
    cudaGetSymbolAddress((void**)&gctx, g_gctx);
    cudaGetSymbolAddress((void**)&Qp, g_Q);
    cudaGetSymbolAddress((void**)&Kp, g_K);
    cudaGetSymbolAddress((void**)&Vp, g_V);
    cudaGetSymbolAddress((void**)&Ap, g_A);

    const int flash_smem = (64 * 64 + 64 * SKP + 64 * 64) * (int)sizeof(float);
    cudaFuncSetAttribute(flash_kernel,
                         cudaFuncAttributeMaxDynamicSharedMemorySize, flash_smem);

    // 1) gated context
    gate_kernel<<<BB * MM / 8, 256>>>(ctx, W1, b1, W2, b2, gctx);

    // 2) projections
    sgemm_kernel<false><<<dim3(INNER / 128, BB * NN / 128), 256>>>(
        x, Wq, nullptr, Qp, BB * NN, INNER, QD);
    sgemm_kernel<false><<<dim3(INNER / 128, BB * MM / 128), 256>>>(
        gctx, Wk, nullptr, Kp, BB * MM, INNER, CD);
    sgemm_kernel<false><<<dim3(INNER / 128, BB * MM / 128), 256>>>(
        gctx, Wv, nullptr, Vp, BB * MM, INNER, CD);

    // 3) attention
    flash_kernel<<<dim3(NN / 64, NH, BB), 256, flash_smem>>>(Qp, Kp, Vp, Ap);

    // 4) output projection + bias -> d_out
    sgemm_kernel<true><<<dim3(QD / 128, BB * NN / 128), 256>>>(
        Ap, Wo, bo, out, BB * NN, QD, INNER);
}

// round 2
// speedup vs baseline: 8.9245x; 8.9245x over previous
#include <cuda_runtime.h>
#include <math.h>

#define BB 4
#define NN 2048
#define MM 2048
#define QD 512
#define CD 64
#define NH 8
#define HD 64
#define INNER 512
#define GATE_HID 32

// Scratch (allocation-free rule: __device__ globals)
__device__ float g_gctx[BB * MM * CD];        //  2 MB gated context
__device__ float g_Q[BB * NN * INNER];        // 16 MB
__device__ float g_K[BB * MM * INNER];        // 16 MB
__device__ float g_V[BB * MM * INNER];        // 16 MB
__device__ float g_A[BB * NN * INNER];        // 16 MB attention output (pre-Wo)

// ---------------------------------------------------------------------------
// tf32 helpers
// ---------------------------------------------------------------------------
__device__ __forceinline__ unsigned f2tf(float x) {
    unsigned u;
    asm("cvt.rna.tf32.f32 %0, %1;" : "=r"(u) : "f"(x));
    return u;
}

__device__ __forceinline__ void mma_tf32(float c[4], const unsigned a[4],
                                         const unsigned b[2]) {
    asm volatile(
        "mma.sync.aligned.m16n8k8.row.col.f32.tf32.tf32.f32 "
        "{%0,%1,%2,%3}, {%4,%5,%6,%7}, {%8,%9}, {%0,%1,%2,%3};"
        : "+f"(c[0]), "+f"(c[1]), "+f"(c[2]), "+f"(c[3])
        : "r"(a[0]), "r"(a[1]), "r"(a[2]), "r"(a[3]), "r"(b[0]), "r"(b[1]));
}

// ---------------------------------------------------------------------------
// Kernel 1: gate = sigmoid(relu(ctx @ W1 + b1) @ W2 + b2); gctx = ctx * gate
// ---------------------------------------------------------------------------
__global__ __launch_bounds__(256) void gate_kernel(
    const float* __restrict__ ctx, const float* __restrict__ W1,
    const float* __restrict__ b1, const float* __restrict__ W2,
    const float* __restrict__ b2, float* __restrict__ gctx) {
    __shared__ float W1s[CD * GATE_HID];
    __shared__ float W2s[GATE_HID];
    __shared__ float b1s[GATE_HID];
    __shared__ float cs[8][CD];

    const int tid = threadIdx.x;
    for (int i = tid; i < CD * GATE_HID; i += 256) W1s[i] = W1[i];
    if (tid < GATE_HID) { W2s[tid] = W2[tid]; b1s[tid] = b1[tid]; }
    __syncthreads();

    const int warp = tid >> 5, lane = tid & 31;
    const int row = blockIdx.x * 8 + warp;
    const float* c = ctx + (size_t)row * CD;
    cs[warp][lane]      = c[lane];
    cs[warp][lane + 32] = c[lane + 32];
    __syncwarp();

    float h = b1s[lane];
#pragma unroll
    for (int i = 0; i < CD; i++) h = fmaf(cs[warp][i], W1s[i * GATE_HID + lane], h);
    h = fmaxf(h, 0.0f);
    float part = h * W2s[lane];
#pragma unroll
    for (int off = 16; off; off >>= 1) part += __shfl_xor_sync(0xffffffffu, part, off);
    const float g = 1.0f / (1.0f + __expf(-(part + b2[0])));

    float* dst = gctx + (size_t)row * CD;
    dst[lane]      = cs[warp][lane] * g;
    dst[lane + 32] = cs[warp][lane + 32] * g;
}

// ---------------------------------------------------------------------------
// Kernel 2: fp32 SGEMM (kept for memory-bound K/V projections, K=64)
// ---------------------------------------------------------------------------
template <bool BIAS>
__global__ __launch_bounds__(256) void sgemm_kernel(
    const float* __restrict__ A, const float* __restrict__ Bm,
    const float* __restrict__ bias, float* __restrict__ C,
    int M, int N, int K) {
    __shared__ float As[8][128];
    __shared__ float Bs[8][128];

    const int bm = blockIdx.y * 128;
    const int bn = blockIdx.x * 128;
    const int tid = threadIdx.x;

    const int arow = tid >> 1, acol = (tid & 1) * 4;
    const int brow = tid >> 5, bcol = (tid & 31) * 4;
    const int tx = tid & 15;
    const int ty = tid >> 4;

    float acc[8][8];
#pragma unroll
    for (int i = 0; i < 8; i++)
#pragma unroll
        for (int j = 0; j < 8; j++) acc[i][j] = 0.0f;

    for (int k0 = 0; k0 < K; k0 += 8) {
        float4 av = *(const float4*)&A[(size_t)(bm + arow) * K + k0 + acol];
        float4 bv = *(const float4*)&Bm[(size_t)(k0 + brow) * N + bn + bcol];
        As[acol + 0][arow] = av.x;
        As[acol + 1][arow] = av.y;
        As[acol + 2][arow] = av.z;
        As[acol + 3][arow] = av.w;
        *(float4*)&Bs[brow][bcol] = bv;
        __syncthreads();

#pragma unroll
        for (int k = 0; k < 8; k++) {
            float a[8], b[8];
            float4 a0 = *(const float4*)&As[k][ty * 4];
            float4 a1 = *(const float4*)&As[k][64 + ty * 4];
            float4 b0 = *(const float4*)&Bs[k][tx * 4];
            float4 b1 = *(const float4*)&Bs[k][64 + tx * 4];
            a[0] = a0.x; a[1] = a0.y; a[2] = a0.z; a[3] = a0.w;
            a[4] = a1.x; a[5] = a1.y; a[6] = a1.z; a[7] = a1.w;
            b[0] = b0.x; b[1] = b0.y; b[2] = b0.z; b[3] = b0.w;
            b[4] = b1.x; b[5] = b1.y; b[6] = b1.z; b[7] = b1.w;
#pragma unroll
            for (int i = 0; i < 8; i++)
#pragma unroll
                for (int j = 0; j < 8; j++) acc[i][j] = fmaf(a[i], b[j], acc[i][j]);
        }
        __syncthreads();
    }

#pragma unroll
    for (int ih = 0; ih < 2; ih++) {
#pragma unroll
        for (int i = 0; i < 4; i++) {
            const int r = bm + ih * 64 + ty * 4 + i;
            float* crow = C + (size_t)r * N + bn;
#pragma unroll
            for (int jh = 0; jh < 2; jh++) {
                const int cbase = jh * 64 + tx * 4;
                float4 v = make_float4(acc[ih * 4 + i][jh * 4 + 0],
                                       acc[ih * 4 + i][jh * 4 + 1],
                                       acc[ih * 4 + i][jh * 4 + 2],
                                       acc[ih * 4 + i][jh * 4 + 3]);
                if (BIAS) {
                    v.x += bias[bn + cbase + 0];
                    v.y += bias[bn + cbase + 1];
                    v.z += bias[bn + cbase + 2];
                    v.w += bias[bn + cbase + 3];
                }
                *(float4*)&crow[cbase] = v;
            }
        }
    }
}

// ---------------------------------------------------------------------------
// Kernel 3: tf32 tensor-core GEMM. 128x128 block, BK=32, 8 warps (4m x 2n),
// warp tile 32x64 via m16n8k8. Conflict-free smem strides (36 / 136 floats).
// ---------------------------------------------------------------------------
#define GAS 36
#define GBS 136

template <bool BIAS>
__global__ __launch_bounds__(256) void mma_gemm(
    const float* __restrict__ A, const float* __restrict__ Bm,
    const float* __restrict__ bias, float* __restrict__ C,
    int M, int N, int K) {
    __shared__ unsigned As[128 * GAS];
    __shared__ unsigned Bs[32 * GBS];

    const int tid = threadIdx.x;
    const int bm = blockIdx.y * 128, bn = blockIdx.x * 128;
    const int wid = tid >> 5, lane = tid & 31, gid = lane >> 2, tig = lane & 3;
    const int wm = (wid & 3) * 32, wn = (wid >> 2) * 64;

    float acc[2][8][4];
#pragma unroll
    for (int mt = 0; mt < 2; mt++)
#pragma unroll
        for (int nt = 0; nt < 8; nt++)
#pragma unroll
            for (int j = 0; j < 4; j++) acc[mt][nt][j] = 0.0f;

    for (int k0 = 0; k0 < K; k0 += 32) {
        __syncthreads();
#pragma unroll
        for (int i = 0; i < 4; i++) {
            int f = tid + i * 256;
            int row = f >> 3, col = (f & 7) * 4;
            float4 v = *(const float4*)&A[(size_t)(bm + row) * K + k0 + col];
            uint4 u = make_uint4(f2tf(v.x), f2tf(v.y), f2tf(v.z), f2tf(v.w));
            *(uint4*)&As[row * GAS + col] = u;
        }
#pragma unroll
        for (int i = 0; i < 4; i++) {
            int f = tid + i * 256;
            int row = f >> 5, col = (f & 31) * 4;
            float4 v = *(const float4*)&Bm[(size_t)(k0 + row) * N + bn + col];
            uint4 u = make_uint4(f2tf(v.x), f2tf(v.y), f2tf(v.z), f2tf(v.w));
            *(uint4*)&Bs[row * GBS + col] = u;
        }
        __syncthreads();

#pragma unroll
        for (int ks = 0; ks < 4; ks++) {
            const int kk = ks * 8;
            unsigned a[2][4];
#pragma unroll
            for (int mt = 0; mt < 2; mt++) {
                int r = wm + mt * 16 + gid;
                a[mt][0] = As[r * GAS + kk + tig];
                a[mt][1] = As[(r + 8) * GAS + kk + tig];
                a[mt][2] = As[r * GAS + kk + tig + 4];
                a[mt][3] = As[(r + 8) * GAS + kk + tig + 4];
            }
#pragma unroll
            for (int nt = 0; nt < 8; nt++) {
                unsigned b[2];
                int c = wn + nt * 8 + gid;
                b[0] = Bs[(kk + tig) * GBS + c];
                b[1] = Bs[(kk + tig + 4) * GBS + c];
                mma_tf32(acc[0][nt], a[0], b);
                mma_tf32(acc[1][nt], a[1], b);
            }
        }
    }

#pragma unroll
    for (int mt = 0; mt < 2; mt++) {
        const int r = bm + wm + mt * 16 + gid;
#pragma unroll
        for (int nt = 0; nt < 8; nt++) {
            const int c = bn + wn + nt * 8 + tig * 2;
            float b0 = 0.0f, b1 = 0.0f;
            if (BIAS) { b0 = bias[c]; b1 = bias[c + 1]; }
            *(float2*)&C[(size_t)r * N + c] =
                make_float2(acc[mt][nt][0] + b0, acc[mt][nt][1] + b1);
            *(float2*)&C[(size_t)(r + 8) * N + c] =
                make_float2(acc[mt][nt][2] + b0, acc[mt][nt][3] + b1);
        }
    }
}

// ---------------------------------------------------------------------------
// Kernel 4: flash attention on tensor cores (tf32 mma, fp32 accum/softmax).
// 64-query tile, 4 warps (warp = 16 rows), 64-key KV tiles, D=64.
// P round-trips through smem (aliases the K tile). Stride 72 floats is
// conflict-free for all fragment access patterns.
// ---------------------------------------------------------------------------
#define FS 72

__global__ __launch_bounds__(128) void flash_mma(
    const float* __restrict__ Q, const float* __restrict__ K,
    const float* __restrict__ V, float* __restrict__ O) {
    extern __shared__ unsigned sh[];
    unsigned* Qs = sh;                 // [64][FS] tf32, Q pre-scaled
    unsigned* Ks = sh + 64 * FS;       // [64][FS] K tile, later P tile
    unsigned* Vs = sh + 2 * 64 * FS;   // [64][FS] V tile [key][d]

    const int b = blockIdx.z, h = blockIdx.y, q0 = blockIdx.x * 64;
    const int tid = threadIdx.x, w = tid >> 5, lane = tid & 31;
    const int gid = lane >> 2, tig = lane & 3;
    const int r0 = w * 16 + gid;       // this thread's first row (r1 = r0+8)

    const float* Qb = Q + ((size_t)b * NN + q0) * INNER + h * HD;
    const float* Kb = K + (size_t)b * MM * INNER + h * HD;
    const float* Vb = V + (size_t)b * MM * INNER + h * HD;

    // Load Q tile (pre-scaled by 1/sqrt(D))
#pragma unroll
    for (int i = 0; i < 8; i++) {
        int f = tid + i * 128;
        int row = f >> 4, col = (f & 15) * 4;
        float4 v = *(const float4*)(Qb + (size_t)row * INNER + col);
        uint4 u = make_uint4(f2tf(v.x * 0.125f), f2tf(v.y * 0.125f),
                             f2tf(v.z * 0.125f), f2tf(v.w * 0.125f));
        *(uint4*)&Qs[row * FS + col] = u;
    }

    float o[8][4];
#pragma unroll
    for (int nt = 0; nt < 8; nt++)
#pragma unroll
        for (int j = 0; j < 4; j++) o[nt][j] = 0.0f;
    float mr0 = -1e30f, mr1 = -1e30f, lr0 = 0.0f, lr1 = 0.0f;

    for (int t = 0; t < MM; t += 64) {
        __syncthreads();  // prior PV reads of Ks(P)/Vs done
#pragma unroll
        for (int i = 0; i < 8; i++) {
            int f = tid + i * 128;
            int row = f >> 4, col = (f & 15) * 4;
            float4 kv = *(const float4*)(Kb + (size_t)(t + row) * INNER + col);
            float4 vv = *(const float4*)(Vb + (size_t)(t + row) * INNER + col);
            *(uint4*)&Ks[row * FS + col] =
                make_uint4(f2tf(kv.x), f2tf(kv.y), f2tf(kv.z), f2tf(kv.w));
            *(uint4*)&Vs[row * FS + col] =
                make_uint4(f2tf(vv.x), f2tf(vv.y), f2tf(vv.z), f2tf(vv.w));
        }
        __syncthreads();

        // S = Q @ K^T  (16x64 per warp)
        float s[8][4];
#pragma unroll
        for (int nt = 0; nt < 8; nt++)
#pragma unroll
            for (int j = 0; j < 4; j++) s[nt][j] = 0.0f;
#pragma unroll
        for (int kk = 0; kk < 8; kk++) {
            const int k0 = kk * 8;
            unsigned a[4];
            a[0] = Qs[r0 * FS + k0 + tig];
            a[1] = Qs[(r0 + 8) * FS + k0 + tig];
            a[2] = Qs[r0 * FS + k0 + tig + 4];
            a[3] = Qs[(r0 + 8) * FS + k0 + tig + 4];
#pragma unroll
            for (int nt = 0; nt < 8; nt++) {
                unsigned bb[2];
                bb[0] = Ks[(nt * 8 + gid) * FS + k0 + tig];
                bb[1] = Ks[(nt * 8 + gid) * FS + k0 + tig + 4];
                mma_tf32(s[nt], a, bb);
            }
        }

        // Online softmax (rows r0, r0+8; stats across the 4 tig lanes)
        float mt0 = s[0][0], mt1 = s[0][2];
#pragma unroll
        for (int nt = 0; nt < 8; nt++) {
            mt0 = fmaxf(mt0, fmaxf(s[nt][0], s[nt][1]));
            mt1 = fmaxf(mt1, fmaxf(s[nt][2], s[nt][3]));
        }
        mt0 = fmaxf(mt0, __shfl_xor_sync(0xffffffffu, mt0, 1));
        mt0 = fmaxf(mt0, __shfl_xor_sync(0xffffffffu, mt0, 2));
        mt1 = fmaxf(mt1, __shfl_xor_sync(0xffffffffu, mt1, 1));
        mt1 = fmaxf(mt1, __shfl_xor_sync(0xffffffffu, mt1, 2));

        const float mn0 = fmaxf(mr0, mt0), mn1 = fmaxf(mr1, mt1);
        const float al0 = __expf(mr0 - mn0), al1 = __expf(mr1 - mn1);
        float ls0 = 0.0f, ls1 = 0.0f;
#pragma unroll
        for (int nt = 0; nt < 8; nt++) {
            s[nt][0] = __expf(s[nt][0] - mn0); ls0 += s[nt][0];
            s[nt][1] = __expf(s[nt][1] - mn0); ls0 += s[nt][1];
            s[nt][2] = __expf(s[nt][2] - mn1); ls1 += s[nt][2];
            s[nt][3] = __expf(s[nt][3] - mn1); ls1 += s[nt][3];
        }
        ls0 += __shfl_xor_sync(0xffffffffu, ls0, 1);
        ls0 += __shfl_xor_sync(0xffffffffu, ls0, 2);
        ls1 += __shfl_xor_sync(0xffffffffu, ls1, 1);
        ls1 += __shfl_xor_sync(0xffffffffu, ls1, 2);
        lr0 = lr0 * al0 + ls0;
        lr1 = lr1 * al1 + ls1;
        mr0 = mn0; mr1 = mn1;
#pragma unroll
        for (int nt = 0; nt < 8; nt++) {
            o[nt][0] *= al0; o[nt][1] *= al0;
            o[nt][2] *= al1; o[nt][3] *= al1;
        }

        __syncthreads();  // all warps done reading Ks before P overwrite
#pragma unroll
        for (int nt = 0; nt < 8; nt++) {
            const int c = nt * 8 + tig * 2;
            *(uint2*)&Ks[r0 * FS + c] =
                make_uint2(f2tf(s[nt][0]), f2tf(s[nt][1]));
            *(uint2*)&Ks[(r0 + 8) * FS + c] =
                make_uint2(f2tf(s[nt][2]), f2tf(s[nt][3]));
        }
        __syncthreads();

        // O += P @ V  (P in Ks alias, V as [key][d])
#pragma unroll
        for (int kk = 0; kk < 8; kk++) {
            const int k0 = kk * 8;
            unsigned a[4];
            a[0] = Ks[r0 * FS + k0 + tig];
            a[1] = Ks[(r0 + 8) * FS + k0 + tig];
            a[2] = Ks[r0 * FS + k0 + tig + 4];
            a[3] = Ks[(r0 + 8) * FS + k0 + tig + 4];
#pragma unroll
            for (int nt = 0; nt < 8; nt++) {
                unsigned bb[2];
                bb[0] = Vs[(k0 + tig) * FS + nt * 8 + gid];
                bb[1] = Vs[(k0 + tig + 4) * FS + nt * 8 + gid];
                mma_tf32(o[nt], a, bb);
            }
        }
    }

    const float i0 = 1.0f / lr0, i1 = 1.0f / lr1;
    float* Ob = O + ((size_t)b * NN + q0) * INNER + h * HD;
#pragma unroll
    for (int nt = 0; nt < 8; nt++) {
        const int c = nt * 8 + tig * 2;
        *(float2*)(Ob + (size_t)r0 * INNER + c) =
            make_float2(o[nt][0] * i0, o[nt][1] * i0);
        *(float2*)(Ob + (size_t)(r0 + 8) * INNER + c) =
            make_float2(o[nt][2] * i1, o[nt][3] * i1);
    }
}

// ---------------------------------------------------------------------------
extern "C" void kernel_launch(void* const* d_in, const int* in_sizes, int n_in,
                              void* d_out, int out_size) {
    const float* x   = (const float*)d_in[0];
    const float* ctx = (const float*)d_in[1];
    const float* Wq  = (const float*)d_in[2];
    const float* Wk  = (const float*)d_in[3];
    const float* Wv  = (const float*)d_in[4];
    const float* W1  = (const float*)d_in[5];
    const float* b1  = (const float*)d_in[6];
    const float* W2  = (const float*)d_in[7];
    const float* b2  = (const float*)d_in[8];
    const float* Wo  = (const float*)d_in[9];
    const float* bo  = (const float*)d_in[10];
    float* out = (float*)d_out;

    float *gctx, *Qp, *Kp, *Vp, *Ap;
    cudaGetSymbolAddress((void**)&gctx, g_gctx);
    cudaGetSymbolAddress((void**)&Qp, g_Q);
    cudaGetSymbolAddress((void**)&Kp, g_K);
    cudaGetSymbolAddress((void**)&Vp, g_V);
    cudaGetSymbolAddress((void**)&Ap, g_A);

    const int flash_smem = 3 * 64 * FS * (int)sizeof(unsigned);  // 55296 B
    cudaFuncSetAttribute(flash_mma,
                         cudaFuncAttributeMaxDynamicSharedMemorySize, flash_smem);

    // 1) gated context
    gate_kernel<<<BB * MM / 8, 256>>>(ctx, W1, b1, W2, b2, gctx);

    // 2) projections: Q via tf32 mma; K/V stay fp32 (memory-bound)
    mma_gemm<false><<<dim3(INNER / 128, BB * NN / 128), 256>>>(
        x, Wq, nullptr, Qp, BB * NN, INNER, QD);
    sgemm_kernel<false><<<dim3(INNER / 128, BB * MM / 128), 256>>>(
        gctx, Wk, nullptr, Kp, BB * MM, INNER, CD);
    sgemm_kernel<false><<<dim3(INNER / 128, BB * MM / 128), 256>>>(
        gctx, Wv, nullptr, Vp, BB * MM, INNER, CD);

    // 3) attention (tensor cores)
    flash_mma<<<dim3(NN / 64, NH, BB), 128, flash_smem>>>(Qp, Kp, Vp, Ap);

    // 4) output projection + bias -> d_out (tf32 mma)
    mma_gemm<true><<<dim3(QD / 128, BB * NN / 128), 256>>>(
        Ap, Wo, bo, out, BB * NN, QD, INNER);
}

// round 3
// speedup vs baseline: 10.0273x; 1.1236x over previous
#include <cuda_runtime.h>
#include <math.h>

#define BB 4
#define NN 2048
#define MM 2048
#define QD 512
#define CD 64
#define NH 8
#define HD 64
#define INNER 512
#define GATE_HID 32

// Scratch (allocation-free rule: __device__ globals)
__device__ float g_gctx[BB * MM * CD];
__device__ float g_Q[BB * NN * INNER];
__device__ float g_K[BB * MM * INNER];
__device__ float g_V[BB * MM * INNER];
__device__ float g_A[BB * NN * INNER];

// ---------------------------------------------------------------------------
// tf32 helpers
// ---------------------------------------------------------------------------
__device__ __forceinline__ unsigned f2tf(float x) {
    unsigned u;
    asm("cvt.rna.tf32.f32 %0, %1;" : "=r"(u) : "f"(x));
    return u;
}

__device__ __forceinline__ void mma_tf32(float c[4], const unsigned a[4],
                                         const unsigned b[2]) {
    asm volatile(
        "mma.sync.aligned.m16n8k8.row.col.f32.tf32.tf32.f32 "
        "{%0,%1,%2,%3}, {%4,%5,%6,%7}, {%8,%9}, {%0,%1,%2,%3};"
        : "+f"(c[0]), "+f"(c[1]), "+f"(c[2]), "+f"(c[3])
        : "r"(a[0]), "r"(a[1]), "r"(a[2]), "r"(a[3]), "r"(b[0]), "r"(b[1]));
}

// ---------------------------------------------------------------------------
// Kernel 1: gate
// ---------------------------------------------------------------------------
__global__ __launch_bounds__(256) void gate_kernel(
    const float* __restrict__ ctx, const float* __restrict__ W1,
    const float* __restrict__ b1, const float* __restrict__ W2,
    const float* __restrict__ b2, float* __restrict__ gctx) {
    __shared__ float W1s[CD * GATE_HID];
    __shared__ float W2s[GATE_HID];
    __shared__ float b1s[GATE_HID];
    __shared__ float cs[8][CD];

    const int tid = threadIdx.x;
    for (int i = tid; i < CD * GATE_HID; i += 256) W1s[i] = W1[i];
    if (tid < GATE_HID) { W2s[tid] = W2[tid]; b1s[tid] = b1[tid]; }
    __syncthreads();

    const int warp = tid >> 5, lane = tid & 31;
    const int row = blockIdx.x * 8 + warp;
    const float* c = ctx + (size_t)row * CD;
    cs[warp][lane]      = c[lane];
    cs[warp][lane + 32] = c[lane + 32];
    __syncwarp();

    float h = b1s[lane];
#pragma unroll
    for (int i = 0; i < CD; i++) h = fmaf(cs[warp][i], W1s[i * GATE_HID + lane], h);
    h = fmaxf(h, 0.0f);
    float part = h * W2s[lane];
#pragma unroll
    for (int off = 16; off; off >>= 1) part += __shfl_xor_sync(0xffffffffu, part, off);
    const float g = 1.0f / (1.0f + __expf(-(part + b2[0])));

    float* dst = gctx + (size_t)row * CD;
    dst[lane]      = cs[warp][lane] * g;
    dst[lane + 32] = cs[warp][lane + 32] * g;
}

// ---------------------------------------------------------------------------
// Kernel 2: fp32 SGEMM (memory-bound K/V projections, K=64)
// ---------------------------------------------------------------------------
template <bool BIAS>
__global__ __launch_bounds__(256) void sgemm_kernel(
    const float* __restrict__ A, const float* __restrict__ Bm,
    const float* __restrict__ bias, float* __restrict__ C,
    int M, int N, int K) {
    __shared__ float As[8][128];
    __shared__ float Bs[8][128];

    const int bm = blockIdx.y * 128;
    const int bn = blockIdx.x * 128;
    const int tid = threadIdx.x;

    const int arow = tid >> 1, acol = (tid & 1) * 4;
    const int brow = tid >> 5, bcol = (tid & 31) * 4;
    const int tx = tid & 15;
    const int ty = tid >> 4;

    float acc[8][8];
#pragma unroll
    for (int i = 0; i < 8; i++)
#pragma unroll
        for (int j = 0; j < 8; j++) acc[i][j] = 0.0f;

    for (int k0 = 0; k0 < K; k0 += 8) {
        float4 av = *(const float4*)&A[(size_t)(bm + arow) * K + k0 + acol];
        float4 bv = *(const float4*)&Bm[(size_t)(k0 + brow) * N + bn + bcol];
        As[acol + 0][arow] = av.x;
        As[acol + 1][arow] = av.y;
        As[acol + 2][arow] = av.z;
        As[acol + 3][arow] = av.w;
        *(float4*)&Bs[brow][bcol] = bv;
        __syncthreads();

#pragma unroll
        for (int k = 0; k < 8; k++) {
            float a[8], b[8];
            float4 a0 = *(const float4*)&As[k][ty * 4];
            float4 a1 = *(const float4*)&As[k][64 + ty * 4];
            float4 b0 = *(const float4*)&Bs[k][tx * 4];
            float4 b1 = *(const float4*)&Bs[k][64 + tx * 4];
            a[0] = a0.x; a[1] = a0.y; a[2] = a0.z; a[3] = a0.w;
            a[4] = a1.x; a[5] = a1.y; a[6] = a1.z; a[7] = a1.w;
            b[0] = b0.x; b[1] = b0.y; b[2] = b0.z; b[3] = b0.w;
            b[4] = b1.x; b[5] = b1.y; b[6] = b1.z; b[7] = b1.w;
#pragma unroll
            for (int i = 0; i < 8; i++)
#pragma unroll
                for (int j = 0; j < 8; j++) acc[i][j] = fmaf(a[i], b[j], acc[i][j]);
        }
        __syncthreads();
    }

#pragma unroll
    for (int ih = 0; ih < 2; ih++) {
#pragma unroll
        for (int i = 0; i < 4; i++) {
            const int r = bm + ih * 64 + ty * 4 + i;
            float* crow = C + (size_t)r * N + bn;
#pragma unroll
            for (int jh = 0; jh < 2; jh++) {
                const int cbase = jh * 64 + tx * 4;
                float4 v = make_float4(acc[ih * 4 + i][jh * 4 + 0],
                                       acc[ih * 4 + i][jh * 4 + 1],
                                       acc[ih * 4 + i][jh * 4 + 2],
                                       acc[ih * 4 + i][jh * 4 + 3]);
                if (BIAS) {
                    v.x += bias[bn + cbase + 0];
                    v.y += bias[bn + cbase + 1];
                    v.z += bias[bn + cbase + 2];
                    v.w += bias[bn + cbase + 3];
                }
                *(float4*)&crow[cbase] = v;
            }
        }
    }
}

// ---------------------------------------------------------------------------
// Kernel 3: tf32 tensor-core GEMM (Wq, Wo)
// ---------------------------------------------------------------------------
#define GAS 36
#define GBS 136

template <bool BIAS>
__global__ __launch_bounds__(256) void mma_gemm(
    const float* __restrict__ A, const float* __restrict__ Bm,
    const float* __restrict__ bias, float* __restrict__ C,
    int M, int N, int K) {
    __shared__ unsigned As[128 * GAS];
    __shared__ unsigned Bs[32 * GBS];

    const int tid = threadIdx.x;
    const int bm = blockIdx.y * 128, bn = blockIdx.x * 128;
    const int wid = tid >> 5, lane = tid & 31, gid = lane >> 2, tig = lane & 3;
    const int wm = (wid & 3) * 32, wn = (wid >> 2) * 64;

    float acc[2][8][4];
#pragma unroll
    for (int mt = 0; mt < 2; mt++)
#pragma unroll
        for (int nt = 0; nt < 8; nt++)
#pragma unroll
            for (int j = 0; j < 4; j++) acc[mt][nt][j] = 0.0f;

    for (int k0 = 0; k0 < K; k0 += 32) {
        __syncthreads();
#pragma unroll
        for (int i = 0; i < 4; i++) {
            int f = tid + i * 256;
            int row = f >> 3, col = (f & 7) * 4;
            float4 v = *(const float4*)&A[(size_t)(bm + row) * K + k0 + col];
            uint4 u = make_uint4(f2tf(v.x), f2tf(v.y), f2tf(v.z), f2tf(v.w));
            *(uint4*)&As[row * GAS + col] = u;
        }
#pragma unroll
        for (int i = 0; i < 4; i++) {
            int f = tid + i * 256;
            int row = f >> 5, col = (f & 31) * 4;
            float4 v = *(const float4*)&Bm[(size_t)(k0 + row) * N + bn + col];
            uint4 u = make_uint4(f2tf(v.x), f2tf(v.y), f2tf(v.z), f2tf(v.w));
            *(uint4*)&Bs[row * GBS + col] = u;
        }
        __syncthreads();

#pragma unroll
        for (int ks = 0; ks < 4; ks++) {
            const int kk = ks * 8;
            unsigned a[2][4];
#pragma unroll
            for (int mt = 0; mt < 2; mt++) {
                int r = wm + mt * 16 + gid;
                a[mt][0] = As[r * GAS + kk + tig];
                a[mt][1] = As[(r + 8) * GAS + kk + tig];
                a[mt][2] = As[r * GAS + kk + tig + 4];
                a[mt][3] = As[(r + 8) * GAS + kk + tig + 4];
            }
#pragma unroll
            for (int nt = 0; nt < 8; nt++) {
                unsigned b[2];
                int c = wn + nt * 8 + gid;
                b[0] = Bs[(kk + tig) * GBS + c];
                b[1] = Bs[(kk + tig + 4) * GBS + c];
                mma_tf32(acc[0][nt], a[0], b);
                mma_tf32(acc[1][nt], a[1], b);
            }
        }
    }

#pragma unroll
    for (int mt = 0; mt < 2; mt++) {
        const int r = bm + wm + mt * 16 + gid;
#pragma unroll
        for (int nt = 0; nt < 8; nt++) {
            const int c = bn + wn + nt * 8 + tig * 2;
            float b0 = 0.0f, b1 = 0.0f;
            if (BIAS) { b0 = bias[c]; b1 = bias[c + 1]; }
            *(float2*)&C[(size_t)r * N + c] =
                make_float2(acc[mt][nt][0] + b0, acc[mt][nt][1] + b1);
            *(float2*)&C[(size_t)(r + 8) * N + c] =
                make_float2(acc[mt][nt][2] + b0, acc[mt][nt][3] + b1);
        }
    }
}

// ---------------------------------------------------------------------------
// Kernel 4: flash attention, tf32 mma.
// CTA: 128 threads (4 warps), 128-query tile. Warp tile: 32 queries x 64 keys
// (2 x m16 chunks). P in a dedicated swizzled buffer (warp-private rows ->
// only __syncwarp between P store and PV).
// Strides: Qs/Ks/Ps = 68 (mod32==4: a/b frag loads conflict-free),
// Vs = 72 (mod32==8: V b-frag loads conflict-free).
// P swizzle: low-3 column bits XOR gid -> stores & loads conflict-free.
// ---------------------------------------------------------------------------
#define QS_S 68
#define VS_S 72

__global__ __launch_bounds__(128) void flash_mma(
    const float* __restrict__ Q, const float* __restrict__ K,
    const float* __restrict__ V, float* __restrict__ O) {
    extern __shared__ unsigned sh[];
    unsigned* Qs = sh;                           // [128][QS_S]
    unsigned* Ks = Qs + 128 * QS_S;              // [64][QS_S]
    unsigned* Vs = Ks + 64 * QS_S;               // [64][VS_S]
    unsigned* Ps = Vs + 64 * VS_S;               // [128][QS_S], swizzled

    const int b = blockIdx.z, h = blockIdx.y, q0 = blockIdx.x * 128;
    const int tid = threadIdx.x, w = tid >> 5, lane = tid & 31;
    const int gid = lane >> 2, tig = lane & 3;
    const int wr = w * 32;  // warp's first query row in tile

    const float* Qb = Q + ((size_t)b * NN + q0) * INNER + h * HD;
    const float* Kb = K + (size_t)b * MM * INNER + h * HD;
    const float* Vb = V + (size_t)b * MM * INNER + h * HD;

    // Stage Q tile (128 rows), pre-scaled by 1/sqrt(D)
#pragma unroll
    for (int i = 0; i < 16; i++) {
        int f = tid + i * 128;
        int row = f >> 4, col = (f & 15) * 4;
        float4 v = *(const float4*)(Qb + (size_t)row * INNER + col);
        uint4 u = make_uint4(f2tf(v.x * 0.125f), f2tf(v.y * 0.125f),
                             f2tf(v.z * 0.125f), f2tf(v.w * 0.125f));
        *(uint4*)&Qs[row * QS_S + col] = u;
    }

    float o[2][8][4];
#pragma unroll
    for (int mt = 0; mt < 2; mt++)
#pragma unroll
        for (int nt = 0; nt < 8; nt++)
#pragma unroll
            for (int j = 0; j < 4; j++) o[mt][nt][j] = 0.0f;
    float mrow[2][2] = {{-1e30f, -1e30f}, {-1e30f, -1e30f}};
    float lrow[2][2] = {{0.0f, 0.0f}, {0.0f, 0.0f}};

    for (int t = 0; t < MM; t += 64) {
        __syncthreads();  // prior tile's reads of Ks/Vs complete
        // Stage K and V tiles (64 rows each)
#pragma unroll
        for (int i = 0; i < 8; i++) {
            int f = tid + i * 128;
            int row = f >> 4, col = (f & 15) * 4;
            float4 kv = *(const float4*)(Kb + (size_t)(t + row) * INNER + col);
            *(uint4*)&Ks[row * QS_S + col] =
                make_uint4(f2tf(kv.x), f2tf(kv.y), f2tf(kv.z), f2tf(kv.w));
        }
#pragma unroll
        for (int i = 0; i < 8; i++) {
            int f = tid + i * 128;
            int row = f >> 4, col = (f & 15) * 4;
            float4 vv = *(const float4*)(Vb + (size_t)(t + row) * INNER + col);
            *(uint4*)&Vs[row * VS_S + col] =
                make_uint4(f2tf(vv.x), f2tf(vv.y), f2tf(vv.z), f2tf(vv.w));
        }
        __syncthreads();

        // S = Q @ K^T  (32x64 per warp)
        float s[2][8][4];
#pragma unroll
        for (int mt = 0; mt < 2; mt++)
#pragma unroll
            for (int nt = 0; nt < 8; nt++)
#pragma unroll
                for (int j = 0; j < 4; j++) s[mt][nt][j] = 0.0f;
#pragma unroll
        for (int kk = 0; kk < 8; kk++) {
            const int k0 = kk * 8;
            unsigned a[2][4];
#pragma unroll
            for (int mt = 0; mt < 2; mt++) {
                int r = wr + mt * 16 + gid;
                a[mt][0] = Qs[r * QS_S + k0 + tig];
                a[mt][1] = Qs[(r + 8) * QS_S + k0 + tig];
                a[mt][2] = Qs[r * QS_S + k0 + tig + 4];
                a[mt][3] = Qs[(r + 8) * QS_S + k0 + tig + 4];
            }
#pragma unroll
            for (int nt = 0; nt < 8; nt++) {
                unsigned bb[2];
                bb[0] = Ks[(nt * 8 + gid) * QS_S + k0 + tig];
                bb[1] = Ks[(nt * 8 + gid) * QS_S + k0 + tig + 4];
                mma_tf32(s[0][nt], a[0], bb);
                mma_tf32(s[1][nt], a[1], bb);
            }
        }

        // Online softmax per mt (rows wr+mt*16+gid and +8)
#pragma unroll
        for (int mt = 0; mt < 2; mt++) {
            float mt0 = s[mt][0][0], mt1 = s[mt][0][2];
#pragma unroll
            for (int nt = 0; nt < 8; nt++) {
                mt0 = fmaxf(mt0, fmaxf(s[mt][nt][0], s[mt][nt][1]));
                mt1 = fmaxf(mt1, fmaxf(s[mt][nt][2], s[mt][nt][3]));
            }
            mt0 = fmaxf(mt0, __shfl_xor_sync(0xffffffffu, mt0, 1));
            mt0 = fmaxf(mt0, __shfl_xor_sync(0xffffffffu, mt0, 2));
            mt1 = fmaxf(mt1, __shfl_xor_sync(0xffffffffu, mt1, 1));
            mt1 = fmaxf(mt1, __shfl_xor_sync(0xffffffffu, mt1, 2));

            const float mn0 = fmaxf(mrow[mt][0], mt0);
            const float mn1 = fmaxf(mrow[mt][1], mt1);
            const float al0 = __expf(mrow[mt][0] - mn0);
            const float al1 = __expf(mrow[mt][1] - mn1);
            float ls0 = 0.0f, ls1 = 0.0f;
#pragma unroll
            for (int nt = 0; nt < 8; nt++) {
                s[mt][nt][0] = __expf(s[mt][nt][0] - mn0); ls0 += s[mt][nt][0];
                s[mt][nt][1] = __expf(s[mt][nt][1] - mn0); ls0 += s[mt][nt][1];
                s[mt][nt][2] = __expf(s[mt][nt][2] - mn1); ls1 += s[mt][nt][2];
                s[mt][nt][3] = __expf(s[mt][nt][3] - mn1); ls1 += s[mt][nt][3];
            }
            ls0 += __shfl_xor_sync(0xffffffffu, ls0, 1);
            ls0 += __shfl_xor_sync(0xffffffffu, ls0, 2);
            ls1 += __shfl_xor_sync(0xffffffffu, ls1, 1);
            ls1 += __shfl_xor_sync(0xffffffffu, ls1, 2);
            lrow[mt][0] = lrow[mt][0] * al0 + ls0;
            lrow[mt][1] = lrow[mt][1] * al1 + ls1;
            mrow[mt][0] = mn0; mrow[mt][1] = mn1;
#pragma unroll
            for (int nt = 0; nt < 8; nt++) {
                o[mt][nt][0] *= al0; o[mt][nt][1] *= al0;
                o[mt][nt][2] *= al1; o[mt][nt][3] *= al1;
            }
        }

        // Store P to warp-private swizzled rows (raw fp32 bits -> tf32 trunc)
#pragma unroll
        for (int mt = 0; mt < 2; mt++) {
            const int r0 = wr + mt * 16 + gid;
#pragma unroll
            for (int nt = 0; nt < 8; nt++) {
                const int cb = nt * 8;
                Ps[r0 * QS_S + cb + ((2 * tig) ^ gid)]     = __float_as_uint(s[mt][nt][0]);
                Ps[r0 * QS_S + cb + ((2 * tig + 1) ^ gid)] = __float_as_uint(s[mt][nt][1]);
                Ps[(r0 + 8) * QS_S + cb + ((2 * tig) ^ gid)]     = __float_as_uint(s[mt][nt][2]);
                Ps[(r0 + 8) * QS_S + cb + ((2 * tig + 1) ^ gid)] = __float_as_uint(s[mt][nt][3]);
            }
        }
        __syncwarp();

        // O += P @ V
#pragma unroll
        for (int kk = 0; kk < 8; kk++) {
            const int k0 = kk * 8;
            unsigned a[2][4];
#pragma unroll
            for (int mt = 0; mt < 2; mt++) {
                int r = wr + mt * 16 + gid;
                a[mt][0] = Ps[r * QS_S + k0 + (tig ^ gid)];
                a[mt][1] = Ps[(r + 8) * QS_S + k0 + (tig ^ gid)];
                a[mt][2] = Ps[r * QS_S + k0 + ((tig + 4) ^ gid)];
                a[mt][3] = Ps[(r + 8) * QS_S + k0 + ((tig + 4) ^ gid)];
            }
#pragma unroll
            for (int nt = 0; nt < 8; nt++) {
                unsigned bb[2];
                bb[0] = Vs[(k0 + tig) * VS_S + nt * 8 + gid];
                bb[1] = Vs[(k0 + tig + 4) * VS_S + nt * 8 + gid];
                mma_tf32(o[0][nt], a[0], bb);
                mma_tf32(o[1][nt], a[1], bb);
            }
        }
    }

    // Epilogue: normalize and store
    float* Ob = O + ((size_t)b * NN + q0) * INNER + h * HD;
#pragma unroll
    for (int mt = 0; mt < 2; mt++) {
        const int r0 = wr + mt * 16 + gid;
        const float i0 = 1.0f / lrow[mt][0], i1 = 1.0f / lrow[mt][1];
#pragma unroll
        for (int nt = 0; nt < 8; nt++) {
            const int c = nt * 8 + tig * 2;
            *(float2*)(Ob + (size_t)r0 * INNER + c) =
                make_float2(o[mt][nt][0] * i0, o[mt][nt][1] * i0);
            *(float2*)(Ob + (size_t)(r0 + 8) * INNER + c) =
                make_float2(o[mt][nt][2] * i1, o[mt][nt][3] * i1);
        }
    }
}

// ---------------------------------------------------------------------------
extern "C" void kernel_launch(void* const* d_in, const int* in_sizes, int n_in,
                              void* d_out, int out_size) {
    const float* x   = (const float*)d_in[0];
    const float* ctx = (const float*)d_in[1];
    const float* Wq  = (const float*)d_in[2];
    const float* Wk  = (const float*)d_in[3];
    const float* Wv  = (const float*)d_in[4];
    const float* W1  = (const float*)d_in[5];
    const float* b1  = (const float*)d_in[6];
    const float* W2  = (const float*)d_in[7];
    const float* b2  = (const float*)d_in[8];
    const float* Wo  = (const float*)d_in[9];
    const float* bo  = (const float*)d_in[10];
    float* out = (float*)d_out;

    float *gctx, *Qp, *Kp, *Vp, *Ap;
    cudaGetSymbolAddress((void**)&gctx, g_gctx);
    cudaGetSymbolAddress((void**)&Qp, g_Q);
    cudaGetSymbolAddress((void**)&Kp, g_K);
    cudaGetSymbolAddress((void**)&Vp, g_V);
    cudaGetSymbolAddress((void**)&Ap, g_A);

    // smem: Qs + Ks + Vs + Ps
    const int flash_smem =
        (128 * QS_S + 64 * QS_S + 64 * VS_S + 128 * QS_S) * (int)sizeof(unsigned);
    cudaFuncSetAttribute(flash_mma,
                         cudaFuncAttributeMaxDynamicSharedMemorySize, flash_smem);

    // 1) gated context
    gate_kernel<<<BB * MM / 8, 256>>>(ctx, W1, b1, W2, b2, gctx);

    // 2) projections
    mma_gemm<false><<<dim3(INNER / 128, BB * NN / 128), 256>>>(
        x, Wq, nullptr, Qp, BB * NN, INNER, QD);
    sgemm_kernel<false><<<dim3(INNER / 128, BB * MM / 128), 256>>>(
        gctx, Wk, nullptr, Kp, BB * MM, INNER, CD);
    sgemm_kernel<false><<<dim3(INNER / 128, BB * MM / 128), 256>>>(
        gctx, Wv, nullptr, Vp, BB * MM, INNER, CD);

    // 3) attention (tensor cores, 128-query CTAs)
    flash_mma<<<dim3(NN / 128, NH, BB), 128, flash_smem>>>(Qp, Kp, Vp, Ap);

    // 4) output projection + bias -> d_out
    mma_gemm<true><<<dim3(QD / 128, BB * NN / 128), 256>>>(
        Ap, Wo, bo, out, BB * NN, QD, INNER);
}

// round 4
// speedup vs baseline: 11.3667x; 1.1336x over previous
#include <cuda_runtime.h>
#include <math.h>

#define BB 4
#define NN 2048
#define MM 2048
#define QD 512
#define CD 64
#define NH 8
#define HD 64
#define INNER 512
#define GATE_HID 32

// Scratch (allocation-free rule: __device__ globals)
__device__ float g_gctx[BB * MM * CD];
__device__ float g_Q[BB * NN * INNER];
__device__ float g_K[BB * MM * INNER];
__device__ float g_V[BB * MM * INNER];
__device__ float g_A[BB * NN * INNER];

// ---------------------------------------------------------------------------
// tf32 helpers
// ---------------------------------------------------------------------------
__device__ __forceinline__ unsigned f2tf(float x) {
    unsigned u;
    asm("cvt.rna.tf32.f32 %0, %1;" : "=r"(u) : "f"(x));
    return u;
}

__device__ __forceinline__ void mma_tf32(float c[4], const unsigned a[4],
                                         const unsigned b[2]) {
    asm volatile(
        "mma.sync.aligned.m16n8k8.row.col.f32.tf32.tf32.f32 "
        "{%0,%1,%2,%3}, {%4,%5,%6,%7}, {%8,%9}, {%0,%1,%2,%3};"
        : "+f"(c[0]), "+f"(c[1]), "+f"(c[2]), "+f"(c[3])
        : "r"(a[0]), "r"(a[1]), "r"(a[2]), "r"(a[3]), "r"(b[0]), "r"(b[1]));
}

// ---------------------------------------------------------------------------
// Kernel 1: gate
// ---------------------------------------------------------------------------
__global__ __launch_bounds__(256) void gate_kernel(
    const float* __restrict__ ctx, const float* __restrict__ W1,
    const float* __restrict__ b1, const float* __restrict__ W2,
    const float* __restrict__ b2, float* __restrict__ gctx) {
    __shared__ float W1s[CD * GATE_HID];
    __shared__ float W2s[GATE_HID];
    __shared__ float b1s[GATE_HID];
    __shared__ float cs[8][CD];

    const int tid = threadIdx.x;
    for (int i = tid; i < CD * GATE_HID; i += 256) W1s[i] = W1[i];
    if (tid < GATE_HID) { W2s[tid] = W2[tid]; b1s[tid] = b1[tid]; }
    __syncthreads();

    const int warp = tid >> 5, lane = tid & 31;
    const int row = blockIdx.x * 8 + warp;
    const float* c = ctx + (size_t)row * CD;
    cs[warp][lane]      = c[lane];
    cs[warp][lane + 32] = c[lane + 32];
    __syncwarp();

    float h = b1s[lane];
#pragma unroll
    for (int i = 0; i < CD; i++) h = fmaf(cs[warp][i], W1s[i * GATE_HID + lane], h);
    h = fmaxf(h, 0.0f);
    float part = h * W2s[lane];
#pragma unroll
    for (int off = 16; off; off >>= 1) part += __shfl_xor_sync(0xffffffffu, part, off);
    const float g = 1.0f / (1.0f + __expf(-(part + b2[0])));

    float* dst = gctx + (size_t)row * CD;
    dst[lane]      = cs[warp][lane] * g;
    dst[lane + 32] = cs[warp][lane + 32] * g;
}

// ---------------------------------------------------------------------------
// Kernel 2: fp32 SGEMM (K/V projections, K=64; fp32 kept for accuracy)
// ---------------------------------------------------------------------------
template <bool BIAS>
__global__ __launch_bounds__(256) void sgemm_kernel(
    const float* __restrict__ A, const float* __restrict__ Bm,
    const float* __restrict__ bias, float* __restrict__ C,
    int M, int N, int K) {
    __shared__ float As[8][128];
    __shared__ float Bs[8][128];

    const int bm = blockIdx.y * 128;
    const int bn = blockIdx.x * 128;
    const int tid = threadIdx.x;

    const int arow = tid >> 1, acol = (tid & 1) * 4;
    const int brow = tid >> 5, bcol = (tid & 31) * 4;
    const int tx = tid & 15;
    const int ty = tid >> 4;

    float acc[8][8];
#pragma unroll
    for (int i = 0; i < 8; i++)
#pragma unroll
        for (int j = 0; j < 8; j++) acc[i][j] = 0.0f;

    for (int k0 = 0; k0 < K; k0 += 8) {
        float4 av = *(const float4*)&A[(size_t)(bm + arow) * K + k0 + acol];
        float4 bv = *(const float4*)&Bm[(size_t)(k0 + brow) * N + bn + bcol];
        As[acol + 0][arow] = av.x;
        As[acol + 1][arow] = av.y;
        As[acol + 2][arow] = av.z;
        As[acol + 3][arow] = av.w;
        *(float4*)&Bs[brow][bcol] = bv;
        __syncthreads();

#pragma unroll
        for (int k = 0; k < 8; k++) {
            float a[8], b[8];
            float4 a0 = *(const float4*)&As[k][ty * 4];
            float4 a1 = *(const float4*)&As[k][64 + ty * 4];
            float4 b0 = *(const float4*)&Bs[k][tx * 4];
            float4 b1 = *(const float4*)&Bs[k][64 + tx * 4];
            a[0] = a0.x; a[1] = a0.y; a[2] = a0.z; a[3] = a0.w;
            a[4] = a1.x; a[5] = a1.y; a[6] = a1.z; a[7] = a1.w;
            b[0] = b0.x; b[1] = b0.y; b[2] = b0.z; b[3] = b0.w;
            b[4] = b1.x; b[5] = b1.y; b[6] = b1.z; b[7] = b1.w;
#pragma unroll
            for (int i = 0; i < 8; i++)
#pragma unroll
                for (int j = 0; j < 8; j++) acc[i][j] = fmaf(a[i], b[j], acc[i][j]);
        }
        __syncthreads();
    }

#pragma unroll
    for (int ih = 0; ih < 2; ih++) {
#pragma unroll
        for (int i = 0; i < 4; i++) {
            const int r = bm + ih * 64 + ty * 4 + i;
            float* crow = C + (size_t)r * N + bn;
#pragma unroll
            for (int jh = 0; jh < 2; jh++) {
                const int cbase = jh * 64 + tx * 4;
                float4 v = make_float4(acc[ih * 4 + i][jh * 4 + 0],
                                       acc[ih * 4 + i][jh * 4 + 1],
                                       acc[ih * 4 + i][jh * 4 + 2],
                                       acc[ih * 4 + i][jh * 4 + 3]);
                if (BIAS) {
                    v.x += bias[bn + cbase + 0];
                    v.y += bias[bn + cbase + 1];
                    v.z += bias[bn + cbase + 2];
                    v.w += bias[bn + cbase + 3];
                }
                *(float4*)&crow[cbase] = v;
            }
        }
    }
}

// ---------------------------------------------------------------------------
// Kernel 3: tf32 tensor-core GEMM (Wq, Wo) — unchanged from round 3
// ---------------------------------------------------------------------------
#define GAS 36
#define GBS 136

template <bool BIAS>
__global__ __launch_bounds__(256) void mma_gemm(
    const float* __restrict__ A, const float* __restrict__ Bm,
    const float* __restrict__ bias, float* __restrict__ C,
    int M, int N, int K) {
    __shared__ unsigned As[128 * GAS];
    __shared__ unsigned Bs[32 * GBS];

    const int tid = threadIdx.x;
    const int bm = blockIdx.y * 128, bn = blockIdx.x * 128;
    const int wid = tid >> 5, lane = tid & 31, gid = lane >> 2, tig = lane & 3;
    const int wm = (wid & 3) * 32, wn = (wid >> 2) * 64;

    float acc[2][8][4];
#pragma unroll
    for (int mt = 0; mt < 2; mt++)
#pragma unroll
        for (int nt = 0; nt < 8; nt++)
#pragma unroll
            for (int j = 0; j < 4; j++) acc[mt][nt][j] = 0.0f;

    for (int k0 = 0; k0 < K; k0 += 32) {
        __syncthreads();
#pragma unroll
        for (int i = 0; i < 4; i++) {
            int f = tid + i * 256;
            int row = f >> 3, col = (f & 7) * 4;
            float4 v = *(const float4*)&A[(size_t)(bm + row) * K + k0 + col];
            uint4 u = make_uint4(f2tf(v.x), f2tf(v.y), f2tf(v.z), f2tf(v.w));
            *(uint4*)&As[row * GAS + col] = u;
        }
#pragma unroll
        for (int i = 0; i < 4; i++) {
            int f = tid + i * 256;
            int row = f >> 5, col = (f & 31) * 4;
            float4 v = *(const float4*)&Bm[(size_t)(k0 + row) * N + bn + col];
            uint4 u = make_uint4(f2tf(v.x), f2tf(v.y), f2tf(v.z), f2tf(v.w));
            *(uint4*)&Bs[row * GBS + col] = u;
        }
        __syncthreads();

#pragma unroll
        for (int ks = 0; ks < 4; ks++) {
            const int kk = ks * 8;
            unsigned a[2][4];
#pragma unroll
            for (int mt = 0; mt < 2; mt++) {
                int r = wm + mt * 16 + gid;
                a[mt][0] = As[r * GAS + kk + tig];
                a[mt][1] = As[(r + 8) * GAS + kk + tig];
                a[mt][2] = As[r * GAS + kk + tig + 4];
                a[mt][3] = As[(r + 8) * GAS + kk + tig + 4];
            }
#pragma unroll
            for (int nt = 0; nt < 8; nt++) {
                unsigned b[2];
                int c = wn + nt * 8 + gid;
                b[0] = Bs[(kk + tig) * GBS + c];
                b[1] = Bs[(kk + tig + 4) * GBS + c];
                mma_tf32(acc[0][nt], a[0], b);
                mma_tf32(acc[1][nt], a[1], b);
            }
        }
    }

#pragma unroll
    for (int mt = 0; mt < 2; mt++) {
        const int r = bm + wm + mt * 16 + gid;
#pragma unroll
        for (int nt = 0; nt < 8; nt++) {
            const int c = bn + wn + nt * 8 + tig * 2;
            float b0 = 0.0f, b1 = 0.0f;
            if (BIAS) { b0 = bias[c]; b1 = bias[c + 1]; }
            *(float2*)&C[(size_t)r * N + c] =
                make_float2(acc[mt][nt][0] + b0, acc[mt][nt][1] + b1);
            *(float2*)&C[(size_t)(r + 8) * N + c] =
                make_float2(acc[mt][nt][2] + b0, acc[mt][nt][3] + b1);
        }
    }
}

// ---------------------------------------------------------------------------
// Kernel 4: flash attention, tf32 mma, latency-optimized.
// CTA: 256 threads (8 warps), 256-query tile, warp tile 32q x 64k (mt=2).
// K/V double-buffered through REGISTERS (LDG next tile overlapped with
// compute; cvt.rna at staging so accuracy is unchanged).
// Strides: Qs/Ks/Ps = 68, Vs = 72 (conflict-free fragment patterns).
// P lives in a swizzled warp-private buffer -> only __syncwarp before PV.
// ---------------------------------------------------------------------------
#define QS_S 68
#define VS_S 72

__global__ __launch_bounds__(256, 1) void flash_mma(
    const float* __restrict__ Q, const float* __restrict__ K,
    const float* __restrict__ V, float* __restrict__ O) {
    extern __shared__ unsigned sh[];
    unsigned* Qs = sh;                            // [256][QS_S]
    unsigned* Ks = Qs + 256 * QS_S;               // [64][QS_S]
    unsigned* Vs = Ks + 64 * QS_S;                // [64][VS_S]
    unsigned* Ps = Vs + 64 * VS_S;                // [256][QS_S], swizzled

    const int b = blockIdx.z, h = blockIdx.y, q0 = blockIdx.x * 256;
    const int tid = threadIdx.x, w = tid >> 5, lane = tid & 31;
    const int gid = lane >> 2, tig = lane & 3;
    const int wr = w * 32;  // warp's first query row in tile

    const float* Qb = Q + ((size_t)b * NN + q0) * INNER + h * HD;
    const float* Kb = K + (size_t)b * MM * INNER + h * HD;
    const float* Vb = V + (size_t)b * MM * INNER + h * HD;

    // Stage Q tile (256 rows), pre-scaled by 1/sqrt(D)
#pragma unroll
    for (int i = 0; i < 16; i++) {
        int f = tid + i * 256;
        int row = f >> 4, col = (f & 15) * 4;
        float4 v = *(const float4*)(Qb + (size_t)row * INNER + col);
        uint4 u = make_uint4(f2tf(v.x * 0.125f), f2tf(v.y * 0.125f),
                             f2tf(v.z * 0.125f), f2tf(v.w * 0.125f));
        *(uint4*)&Qs[row * QS_S + col] = u;
    }

    float o[2][8][4];
#pragma unroll
    for (int mt = 0; mt < 2; mt++)
#pragma unroll
        for (int nt = 0; nt < 8; nt++)
#pragma unroll
            for (int j = 0; j < 4; j++) o[mt][nt][j] = 0.0f;
    float mrow[2][2] = {{-1e30f, -1e30f}, {-1e30f, -1e30f}};
    float lrow[2][2] = {{0.0f, 0.0f}, {0.0f, 0.0f}};

    // Per-thread staging coords: 4 float4 for K, 4 for V per tile
    const int srow = tid >> 4, scol = (tid & 15) * 4;  // +64 rows per i via f
    float4 pk[4], pv[4];
#pragma unroll
    for (int i = 0; i < 4; i++) {
        int f = tid + i * 256;
        int row = f >> 4, col = (f & 15) * 4;
        pk[i] = *(const float4*)(Kb + (size_t)row * INNER + col);
        pv[i] = *(const float4*)(Vb + (size_t)row * INNER + col);
    }
    (void)srow; (void)scol;

    for (int t = 0; t < MM; t += 64) {
        // Store prefetched K/V tile (cvt.rna at staging)
#pragma unroll
        for (int i = 0; i < 4; i++) {
            int f = tid + i * 256;
            int row = f >> 4, col = (f & 15) * 4;
            *(uint4*)&Ks[row * QS_S + col] =
                make_uint4(f2tf(pk[i].x), f2tf(pk[i].y), f2tf(pk[i].z), f2tf(pk[i].w));
            *(uint4*)&Vs[row * VS_S + col] =
                make_uint4(f2tf(pv[i].x), f2tf(pv[i].y), f2tf(pv[i].z), f2tf(pv[i].w));
        }
        __syncthreads();

        // Prefetch next tile into registers (latency overlapped with compute)
        if (t + 64 < MM) {
#pragma unroll
            for (int i = 0; i < 4; i++) {
                int f = tid + i * 256;
                int row = f >> 4, col = (f & 15) * 4;
                pk[i] = *(const float4*)(Kb + (size_t)(t + 64 + row) * INNER + col);
                pv[i] = *(const float4*)(Vb + (size_t)(t + 64 + row) * INNER + col);
            }
        }

        // S = Q @ K^T  (32x64 per warp)
        float s[2][8][4];
#pragma unroll
        for (int mt = 0; mt < 2; mt++)
#pragma unroll
            for (int nt = 0; nt < 8; nt++)
#pragma unroll
                for (int j = 0; j < 4; j++) s[mt][nt][j] = 0.0f;
#pragma unroll
        for (int kk = 0; kk < 8; kk++) {
            const int k0 = kk * 8;
            unsigned a[2][4];
#pragma unroll
            for (int mt = 0; mt < 2; mt++) {
                int r = wr + mt * 16 + gid;
                a[mt][0] = Qs[r * QS_S + k0 + tig];
                a[mt][1] = Qs[(r + 8) * QS_S + k0 + tig];
                a[mt][2] = Qs[r * QS_S + k0 + tig + 4];
                a[mt][3] = Qs[(r + 8) * QS_S + k0 + tig + 4];
            }
#pragma unroll
            for (int nt = 0; nt < 8; nt++) {
                unsigned bb[2];
                bb[0] = Ks[(nt * 8 + gid) * QS_S + k0 + tig];
                bb[1] = Ks[(nt * 8 + gid) * QS_S + k0 + tig + 4];
                mma_tf32(s[0][nt], a[0], bb);
                mma_tf32(s[1][nt], a[1], bb);
            }
        }

        // Online softmax per mt (rows wr+mt*16+gid and +8)
#pragma unroll
        for (int mt = 0; mt < 2; mt++) {
            float mt0 = s[mt][0][0], mt1 = s[mt][0][2];
#pragma unroll
            for (int nt = 0; nt < 8; nt++) {
                mt0 = fmaxf(mt0, fmaxf(s[mt][nt][0], s[mt][nt][1]));
                mt1 = fmaxf(mt1, fmaxf(s[mt][nt][2], s[mt][nt][3]));
            }
            mt0 = fmaxf(mt0, __shfl_xor_sync(0xffffffffu, mt0, 1));
            mt0 = fmaxf(mt0, __shfl_xor_sync(0xffffffffu, mt0, 2));
            mt1 = fmaxf(mt1, __shfl_xor_sync(0xffffffffu, mt1, 1));
            mt1 = fmaxf(mt1, __shfl_xor_sync(0xffffffffu, mt1, 2));

            const float mn0 = fmaxf(mrow[mt][0], mt0);
            const float mn1 = fmaxf(mrow[mt][1], mt1);
            const float al0 = __expf(mrow[mt][0] - mn0);
            const float al1 = __expf(mrow[mt][1] - mn1);
            float ls0 = 0.0f, ls1 = 0.0f;
#pragma unroll
            for (int nt = 0; nt < 8; nt++) {
                s[mt][nt][0] = __expf(s[mt][nt][0] - mn0); ls0 += s[mt][nt][0];
                s[mt][nt][1] = __expf(s[mt][nt][1] - mn0); ls0 += s[mt][nt][1];
                s[mt][nt][2] = __expf(s[mt][nt][2] - mn1); ls1 += s[mt][nt][2];
                s[mt][nt][3] = __expf(s[mt][nt][3] - mn1); ls1 += s[mt][nt][3];
            }
            ls0 += __shfl_xor_sync(0xffffffffu, ls0, 1);
            ls0 += __shfl_xor_sync(0xffffffffu, ls0, 2);
            ls1 += __shfl_xor_sync(0xffffffffu, ls1, 1);
            ls1 += __shfl_xor_sync(0xffffffffu, ls1, 2);
            lrow[mt][0] = lrow[mt][0] * al0 + ls0;
            lrow[mt][1] = lrow[mt][1] * al1 + ls1;
            mrow[mt][0] = mn0; mrow[mt][1] = mn1;
#pragma unroll
            for (int nt = 0; nt < 8; nt++) {
                o[mt][nt][0] *= al0; o[mt][nt][1] *= al0;
                o[mt][nt][2] *= al1; o[mt][nt][3] *= al1;
            }
        }

        // Store P to warp-private swizzled rows (raw fp32 bits -> tf32 trunc)
#pragma unroll
        for (int mt = 0; mt < 2; mt++) {
            const int r0 = wr + mt * 16 + gid;
#pragma unroll
            for (int nt = 0; nt < 8; nt++) {
                const int cb = nt * 8;
                Ps[r0 * QS_S + cb + ((2 * tig) ^ gid)]     = __float_as_uint(s[mt][nt][0]);
                Ps[r0 * QS_S + cb + ((2 * tig + 1) ^ gid)] = __float_as_uint(s[mt][nt][1]);
                Ps[(r0 + 8) * QS_S + cb + ((2 * tig) ^ gid)]     = __float_as_uint(s[mt][nt][2]);
                Ps[(r0 + 8) * QS_S + cb + ((2 * tig + 1) ^ gid)] = __float_as_uint(s[mt][nt][3]);
            }
        }
        __syncwarp();

        // O += P @ V
#pragma unroll
        for (int kk = 0; kk < 8; kk++) {
            const int k0 = kk * 8;
            unsigned a[2][4];
#pragma unroll
            for (int mt = 0; mt < 2; mt++) {
                int r = wr + mt * 16 + gid;
                a[mt][0] = Ps[r * QS_S + k0 + (tig ^ gid)];
                a[mt][1] = Ps[(r + 8) * QS_S + k0 + (tig ^ gid)];
                a[mt][2] = Ps[r * QS_S + k0 + ((tig + 4) ^ gid)];
                a[mt][3] = Ps[(r + 8) * QS_S + k0 + ((tig + 4) ^ gid)];
            }
#pragma unroll
            for (int nt = 0; nt < 8; nt++) {
                unsigned bb[2];
                bb[0] = Vs[(k0 + tig) * VS_S + nt * 8 + gid];
                bb[1] = Vs[(k0 + tig + 4) * VS_S + nt * 8 + gid];
                mma_tf32(o[0][nt], a[0], bb);
                mma_tf32(o[1][nt], a[1], bb);
            }
        }
        __syncthreads();  // all warps done reading Ks/Vs before next staging
    }

    // Epilogue: normalize and store
    float* Ob = O + ((size_t)b * NN + q0) * INNER + h * HD;
#pragma unroll
    for (int mt = 0; mt < 2; mt++) {
        const int r0 = wr + mt * 16 + gid;
        const float i0 = 1.0f / lrow[mt][0], i1 = 1.0f / lrow[mt][1];
#pragma unroll
        for (int nt = 0; nt < 8; nt++) {
            const int c = nt * 8 + tig * 2;
            *(float2*)(Ob + (size_t)r0 * INNER + c) =
                make_float2(o[mt][nt][0] * i0, o[mt][nt][1] * i0);
            *(float2*)(Ob + (size_t)(r0 + 8) * INNER + c) =
                make_float2(o[mt][nt][2] * i1, o[mt][nt][3] * i1);
        }
    }
}

// ---------------------------------------------------------------------------
extern "C" void kernel_launch(void* const* d_in, const int* in_sizes, int n_in,
                              void* d_out, int out_size) {
    const float* x   = (const float*)d_in[0];
    const float* ctx = (const float*)d_in[1];
    const float* Wq  = (const float*)d_in[2];
    const float* Wk  = (const float*)d_in[3];
    const float* Wv  = (const float*)d_in[4];
    const float* W1  = (const float*)d_in[5];
    const float* b1  = (const float*)d_in[6];
    const float* W2  = (const float*)d_in[7];
    const float* b2  = (const float*)d_in[8];
    const float* Wo  = (const float*)d_in[9];
    const float* bo  = (const float*)d_in[10];
    float* out = (float*)d_out;

    float *gctx, *Qp, *Kp, *Vp, *Ap;
    cudaGetSymbolAddress((void**)&gctx, g_gctx);
    cudaGetSymbolAddress((void**)&Qp, g_Q);
    cudaGetSymbolAddress((void**)&Kp, g_K);
    cudaGetSymbolAddress((void**)&Vp, g_V);
    cudaGetSymbolAddress((void**)&Ap, g_A);

    // smem: Qs + Ks + Vs + Ps  = (256*68 + 64*68 + 64*72 + 256*68) words
    const int flash_smem =
        (256 * QS_S + 64 * QS_S + 64 * VS_S + 256 * QS_S) * (int)sizeof(unsigned);
    cudaFuncSetAttribute(flash_mma,
                         cudaFuncAttributeMaxDynamicSharedMemorySize, flash_smem);

    // 1) gated context
    gate_kernel<<<BB * MM / 8, 256>>>(ctx, W1, b1, W2, b2, gctx);

    // 2) projections
    mma_gemm<false><<<dim3(INNER / 128, BB * NN / 128), 256>>>(
        x, Wq, nullptr, Qp, BB * NN, INNER, QD);
    sgemm_kernel<false><<<dim3(INNER / 128, BB * MM / 128), 256>>>(
        gctx, Wk, nullptr, Kp, BB * MM, INNER, CD);
    sgemm_kernel<false><<<dim3(INNER / 128, BB * MM / 128), 256>>>(
        gctx, Wv, nullptr, Vp, BB * MM, INNER, CD);

    // 3) attention (tensor cores, 256-query CTAs, 8 warps)
    flash_mma<<<dim3(NN / 256, NH, BB), 256, flash_smem>>>(Qp, Kp, Vp, Ap);

    // 4) output projection + bias -> d_out
    mma_gemm<true><<<dim3(QD / 128, BB * NN / 128), 256>>>(
        Ap, Wo, bo, out, BB * NN, QD, INNER);
}

// round 5
// speedup vs baseline: 17.9075x; 1.5754x over previous
#include <cuda_runtime.h>
#include <cuda_fp16.h>
#include <math.h>

#define BB 4
#define NN 2048
#define MM 2048
#define QD 512
#define CD 64
#define NH 8
#define HD 64
#define INNER 512
#define GATE_HID 32

// Scratch (allocation-free rule: __device__ globals)
__device__ float  g_gctx[BB * MM * CD];          //  2 MB gated context
__device__ __half g_Qh[BB * NN * INNER];         //  8 MB f16 Q (row-major, pre-scaled)
__device__ __half g_Kh[BB * MM * INNER];         //  8 MB f16 K (row-major)
__device__ __half g_Vt[BB * NH * HD * MM];       //  8 MB f16 V transposed [b][h][d][M]
__device__ float  g_A[BB * NN * INNER];          // 16 MB attention output (pre-Wo)

// ---------------------------------------------------------------------------
// helpers
// ---------------------------------------------------------------------------
__device__ __forceinline__ unsigned f2tf(float x) {
    unsigned u;
    asm("cvt.rna.tf32.f32 %0, %1;" : "=r"(u) : "f"(x));
    return u;
}

// pack two f32 into f16x2: low half = lo, high half = hi
__device__ __forceinline__ unsigned pack_h2(float lo, float hi) {
    unsigned d;
    asm("cvt.rn.f16x2.f32 %0, %1, %2;" : "=r"(d) : "f"(hi), "f"(lo));
    return d;
}

__device__ __forceinline__ void mma_tf32(float c[4], const unsigned a[4],
                                         const unsigned b[2]) {
    asm volatile(
        "mma.sync.aligned.m16n8k8.row.col.f32.tf32.tf32.f32 "
        "{%0,%1,%2,%3}, {%4,%5,%6,%7}, {%8,%9}, {%0,%1,%2,%3};"
        : "+f"(c[0]), "+f"(c[1]), "+f"(c[2]), "+f"(c[3])
        : "r"(a[0]), "r"(a[1]), "r"(a[2]), "r"(a[3]), "r"(b[0]), "r"(b[1]));
}

__device__ __forceinline__ void mma_f16(float c[4], const unsigned a[4],
                                        unsigned b0, unsigned b1) {
    asm volatile(
        "mma.sync.aligned.m16n8k16.row.col.f32.f16.f16.f32 "
        "{%0,%1,%2,%3}, {%4,%5,%6,%7}, {%8,%9}, {%0,%1,%2,%3};"
        : "+f"(c[0]), "+f"(c[1]), "+f"(c[2]), "+f"(c[3])
        : "r"(a[0]), "r"(a[1]), "r"(a[2]), "r"(a[3]), "r"(b0), "r"(b1));
}

// ---------------------------------------------------------------------------
// Kernel 1: gate = sigmoid(relu(ctx @ W1 + b1) @ W2 + b2); gctx = ctx * gate
// ---------------------------------------------------------------------------
__global__ __launch_bounds__(256) void gate_kernel(
    const float* __restrict__ ctx, const float* __restrict__ W1,
    const float* __restrict__ b1, const float* __restrict__ W2,
    const float* __restrict__ b2, float* __restrict__ gctx) {
    __shared__ float W1s[CD * GATE_HID];
    __shared__ float W2s[GATE_HID];
    __shared__ float b1s[GATE_HID];
    __shared__ float cs[8][CD];

    const int tid = threadIdx.x;
    for (int i = tid; i < CD * GATE_HID; i += 256) W1s[i] = W1[i];
    if (tid < GATE_HID) { W2s[tid] = W2[tid]; b1s[tid] = b1[tid]; }
    __syncthreads();

    const int warp = tid >> 5, lane = tid & 31;
    const int row = blockIdx.x * 8 + warp;
    const float* c = ctx + (size_t)row * CD;
    cs[warp][lane]      = c[lane];
    cs[warp][lane + 32] = c[lane + 32];
    __syncwarp();

    float h = b1s[lane];
#pragma unroll
    for (int i = 0; i < CD; i++) h = fmaf(cs[warp][i], W1s[i * GATE_HID + lane], h);
    h = fmaxf(h, 0.0f);
    float part = h * W2s[lane];
#pragma unroll
    for (int off = 16; off; off >>= 1) part += __shfl_xor_sync(0xffffffffu, part, off);
    const float g = 1.0f / (1.0f + __expf(-(part + b2[0])));

    float* dst = gctx + (size_t)row * CD;
    dst[lane]      = cs[warp][lane] * g;
    dst[lane + 32] = cs[warp][lane + 32] * g;
}

// ---------------------------------------------------------------------------
// Kernel 2: fp32 SGEMM core (K/V projections, K=64), templated epilogue:
// EP=0: f16 row-major out. EP=1: f16 transposed out Vt[b][h][d][M].
// ---------------------------------------------------------------------------
template <int EP>
__global__ __launch_bounds__(256) void sgemm_f16(
    const float* __restrict__ A, const float* __restrict__ Bm,
    __half* __restrict__ C, int M, int N, int K) {
    __shared__ float As[8][128];
    __shared__ float Bs[8][128];

    const int bm = blockIdx.y * 128;
    const int bn = blockIdx.x * 128;
    const int tid = threadIdx.x;

    const int arow = tid >> 1, acol = (tid & 1) * 4;
    const int brow = tid >> 5, bcol = (tid & 31) * 4;
    const int tx = tid & 15;
    const int ty = tid >> 4;

    float acc[8][8];
#pragma unroll
    for (int i = 0; i < 8; i++)
#pragma unroll
        for (int j = 0; j < 8; j++) acc[i][j] = 0.0f;

    for (int k0 = 0; k0 < K; k0 += 8) {
        float4 av = *(const float4*)&A[(size_t)(bm + arow) * K + k0 + acol];
        float4 bv = *(const float4*)&Bm[(size_t)(k0 + brow) * N + bn + bcol];
        As[acol + 0][arow] = av.x;
        As[acol + 1][arow] = av.y;
        As[acol + 2][arow] = av.z;
        As[acol + 3][arow] = av.w;
        *(float4*)&Bs[brow][bcol] = bv;
        __syncthreads();

#pragma unroll
        for (int k = 0; k < 8; k++) {
            float a[8], b[8];
            float4 a0 = *(const float4*)&As[k][ty * 4];
            float4 a1 = *(const float4*)&As[k][64 + ty * 4];
            float4 b0 = *(const float4*)&Bs[k][tx * 4];
            float4 b1 = *(const float4*)&Bs[k][64 + tx * 4];
            a[0] = a0.x; a[1] = a0.y; a[2] = a0.z; a[3] = a0.w;
            a[4] = a1.x; a[5] = a1.y; a[6] = a1.z; a[7] = a1.w;
            b[0] = b0.x; b[1] = b0.y; b[2] = b0.z; b[3] = b0.w;
            b[4] = b1.x; b[5] = b1.y; b[6] = b1.z; b[7] = b1.w;
#pragma unroll
            for (int i = 0; i < 8; i++)
#pragma unroll
                for (int j = 0; j < 8; j++) acc[i][j] = fmaf(a[i], b[j], acc[i][j]);
        }
        __syncthreads();
    }

    if (EP == 0) {
        // f16 row-major
        unsigned* Cw = (unsigned*)C;
        const int nw = N >> 1;
#pragma unroll
        for (int ih = 0; ih < 2; ih++) {
#pragma unroll
            for (int i = 0; i < 4; i++) {
                const int r = bm + ih * 64 + ty * 4 + i;
#pragma unroll
                for (int jh = 0; jh < 2; jh++) {
                    const int cbase = bn + jh * 64 + tx * 4;
                    uint2 u;
                    u.x = pack_h2(acc[ih * 4 + i][jh * 4 + 0], acc[ih * 4 + i][jh * 4 + 1]);
                    u.y = pack_h2(acc[ih * 4 + i][jh * 4 + 2], acc[ih * 4 + i][jh * 4 + 3]);
                    *(uint2*)&Cw[(size_t)r * nw + (cbase >> 1)] = u;
                }
            }
        }
    } else {
        // f16 transposed: Vt[b][h][d][MM]; rows are tokens (b*MM+tok), cols h*64+d
        unsigned* Cw = (unsigned*)C;
#pragma unroll
        for (int jh = 0; jh < 2; jh++) {
#pragma unroll
            for (int j = 0; j < 4; j++) {
                const int c = bn + jh * 64 + tx * 4 + j;
                const int hh = c >> 6, d = c & 63;
#pragma unroll
                for (int ih = 0; ih < 2; ih++) {
                    const int grow = bm + ih * 64 + ty * 4;  // 4 contiguous tokens
                    const int bb = grow >> 11;
                    const int tok = grow & 2047;
                    uint2 u;
                    u.x = pack_h2(acc[ih * 4 + 0][jh * 4 + j], acc[ih * 4 + 1][jh * 4 + j]);
                    u.y = pack_h2(acc[ih * 4 + 2][jh * 4 + j], acc[ih * 4 + 3][jh * 4 + j]);
                    size_t idx = (((size_t)bb * NH + hh) * HD + d) * MM + tok;
                    *(uint2*)&Cw[idx >> 1] = u;
                }
            }
        }
    }
}

// ---------------------------------------------------------------------------
// Kernel 3: tf32 tensor-core GEMM. F16OUT=1: write f16 (pre-scaled by SCL).
// BIAS only used when F16OUT=0.
// ---------------------------------------------------------------------------
#define GAS 36
#define GBS 136

template <bool BIAS, bool F16OUT>
__global__ __launch_bounds__(256) void mma_gemm(
    const float* __restrict__ A, const float* __restrict__ Bm,
    const float* __restrict__ bias, void* __restrict__ Cv,
    int M, int N, int K, float scl) {
    __shared__ unsigned As[128 * GAS];
    __shared__ unsigned Bs[32 * GBS];

    const int tid = threadIdx.x;
    const int bm = blockIdx.y * 128, bn = blockIdx.x * 128;
    const int wid = tid >> 5, lane = tid & 31, gid = lane >> 2, tig = lane & 3;
    const int wm = (wid & 3) * 32, wn = (wid >> 2) * 64;

    float acc[2][8][4];
#pragma unroll
    for (int mt = 0; mt < 2; mt++)
#pragma unroll
        for (int nt = 0; nt < 8; nt++)
#pragma unroll
            for (int j = 0; j < 4; j++) acc[mt][nt][j] = 0.0f;

    for (int k0 = 0; k0 < K; k0 += 32) {
        __syncthreads();
#pragma unroll
        for (int i = 0; i < 4; i++) {
            int f = tid + i * 256;
            int row = f >> 3, col = (f & 7) * 4;
            float4 v = *(const float4*)&A[(size_t)(bm + row) * K + k0 + col];
            uint4 u = make_uint4(f2tf(v.x), f2tf(v.y), f2tf(v.z), f2tf(v.w));
            *(uint4*)&As[row * GAS + col] = u;
        }
#pragma unroll
        for (int i = 0; i < 4; i++) {
            int f = tid + i * 256;
            int row = f >> 5, col = (f & 31) * 4;
            float4 v = *(const float4*)&Bm[(size_t)(k0 + row) * N + bn + col];
            uint4 u = make_uint4(f2tf(v.x), f2tf(v.y), f2tf(v.z), f2tf(v.w));
            *(uint4*)&Bs[row * GBS + col] = u;
        }
        __syncthreads();

#pragma unroll
        for (int ks = 0; ks < 4; ks++) {
            const int kk = ks * 8;
            unsigned a[2][4];
#pragma unroll
            for (int mt = 0; mt < 2; mt++) {
                int r = wm + mt * 16 + gid;
                a[mt][0] = As[r * GAS + kk + tig];
                a[mt][1] = As[(r + 8) * GAS + kk + tig];
                a[mt][2] = As[r * GAS + kk + tig + 4];
                a[mt][3] = As[(r + 8) * GAS + kk + tig + 4];
            }
#pragma unroll
            for (int nt = 0; nt < 8; nt++) {
                unsigned b[2];
                int c = wn + nt * 8 + gid;
                b[0] = Bs[(kk + tig) * GBS + c];
                b[1] = Bs[(kk + tig + 4) * GBS + c];
                mma_tf32(acc[0][nt], a[0], b);
                mma_tf32(acc[1][nt], a[1], b);
            }
        }
    }

    if (F16OUT) {
        unsigned* Cw = (unsigned*)Cv;
        const int nw = N >> 1;
#pragma unroll
        for (int mt = 0; mt < 2; mt++) {
            const int r = bm + wm + mt * 16 + gid;
#pragma unroll
            for (int nt = 0; nt < 8; nt++) {
                const int c = bn + wn + nt * 8 + tig * 2;
                Cw[(size_t)r * nw + (c >> 1)] =
                    pack_h2(acc[mt][nt][0] * scl, acc[mt][nt][1] * scl);
                Cw[(size_t)(r + 8) * nw + (c >> 1)] =
                    pack_h2(acc[mt][nt][2] * scl, acc[mt][nt][3] * scl);
            }
        }
    } else {
        float* C = (float*)Cv;
#pragma unroll
        for (int mt = 0; mt < 2; mt++) {
            const int r = bm + wm + mt * 16 + gid;
#pragma unroll
            for (int nt = 0; nt < 8; nt++) {
                const int c = bn + wn + nt * 8 + tig * 2;
                float b0 = 0.0f, b1 = 0.0f;
                if (BIAS) { b0 = bias[c]; b1 = bias[c + 1]; }
                *(float2*)&C[(size_t)r * N + c] =
                    make_float2(acc[mt][nt][0] + b0, acc[mt][nt][1] + b1);
                *(float2*)&C[(size_t)(r + 8) * N + c] =
                    make_float2(acc[mt][nt][2] + b0, acc[mt][nt][3] + b1);
            }
        }
    }
}

// ---------------------------------------------------------------------------
// Kernel 4: flash attention, f16 mma (m16n8k16), fp32 accum/softmax.
// 256-query CTA, 8 warps, warp tile 32q x 64k. Q frags hoisted to registers.
// P C-frag packs directly into the PV A-frag (no smem round-trip).
// K row-major f16; V pre-transposed f16 [d][M]. Double-buffered K/V tiles
// with register prefetch; ONE __syncthreads per tile.
// Tile rows are 32 u32 words (f16x2); stride 36 words -> conflict-free.
// ---------------------------------------------------------------------------
#define KW 36

__global__ __launch_bounds__(256, 1) void flash_f16(
    const __half* __restrict__ Q, const __half* __restrict__ K,
    const __half* __restrict__ V, float* __restrict__ O) {
    extern __shared__ unsigned sh[];
    unsigned* Qs = sh;                  // [256][KW]
    unsigned* Ks = Qs + 256 * KW;       // [2][64][KW]
    unsigned* Vs = Ks + 2 * 64 * KW;    // [2][64][KW]

    const int b = blockIdx.z, h = blockIdx.y, q0 = blockIdx.x * 256;
    const int tid = threadIdx.x, w = tid >> 5, lane = tid & 31;
    const int gid = lane >> 2, tig = lane & 3;
    const int wr = w * 32;

    const __half* Qb = Q + ((size_t)b * NN + q0) * INNER + h * HD;
    const __half* Kb = K + (size_t)b * MM * INNER + h * HD;
    const __half* Vb = V + ((size_t)b * NH + h) * HD * MM;  // [d][M]

    // Stage Q tile (256 rows x 64 f16 = 128B/row)
#pragma unroll
    for (int i = 0; i < 8; i++) {
        int f = tid + i * 256;
        int row = f >> 3, g = f & 7;
        uint4 v = *(const uint4*)(Qb + (size_t)row * INNER + g * 8);
        *(uint4*)&Qs[row * KW + g * 4] = v;
    }

    // Prefetch K/V tile 0
    uint4 pk[2], pv[2];
#pragma unroll
    for (int i = 0; i < 2; i++) {
        int f = tid + i * 256;
        int row = f >> 3, g = f & 7;
        pk[i] = *(const uint4*)(Kb + (size_t)row * INNER + g * 8);
        pv[i] = *(const uint4*)(Vb + (size_t)row * MM + g * 8);
    }
    __syncthreads();

    // Hoist Q fragments (each warp reads only its own 32 rows)
    unsigned qf[4][2][4];
#pragma unroll
    for (int kk = 0; kk < 4; kk++)
#pragma unroll
        for (int mt = 0; mt < 2; mt++) {
            int r = wr + mt * 16 + gid;
            qf[kk][mt][0] = Qs[r * KW + kk * 8 + tig];
            qf[kk][mt][1] = Qs[(r + 8) * KW + kk * 8 + tig];
            qf[kk][mt][2] = Qs[r * KW + kk * 8 + tig + 4];
            qf[kk][mt][3] = Qs[(r + 8) * KW + kk * 8 + tig + 4];
        }

    float o[2][8][4];
#pragma unroll
    for (int mt = 0; mt < 2; mt++)
#pragma unroll
        for (int nt = 0; nt < 8; nt++)
#pragma unroll
            for (int j = 0; j < 4; j++) o[mt][nt][j] = 0.0f;
    float mrow[2][2] = {{-1e30f, -1e30f}, {-1e30f, -1e30f}};
    float lrow[2][2] = {{0.0f, 0.0f}, {0.0f, 0.0f}};

    const int srow = tid >> 3, sg = (tid & 7) * 4;  // staging coords (i=0 part)

    for (int t = 0; t < MM; t += 64) {
        const int p = (t >> 6) & 1;
        unsigned* Kp = Ks + p * 64 * KW;
        unsigned* Vp = Vs + p * 64 * KW;

        // Store prefetched tile (writes to buf p; safe pre-barrier: readers of
        // buf p from tile t-2 all finished before barrier(t-1)).
#pragma unroll
        for (int i = 0; i < 2; i++) {
            int row = srow + i * 32;
            *(uint4*)&Kp[row * KW + sg] = pk[i];
            *(uint4*)&Vp[row * KW + sg] = pv[i];
        }
        __syncthreads();

        // Prefetch next tile
        if (t + 64 < MM) {
#pragma unroll
            for (int i = 0; i < 2; i++) {
                int row = srow + i * 32;
                pk[i] = *(const uint4*)(Kb + (size_t)(t + 64 + row) * INNER + sg * 2);
                pv[i] = *(const uint4*)(Vb + (size_t)row * MM + t + 64 + sg * 2);
            }
        }

        // S = Q @ K^T  (32x64 per warp)
        float s[2][8][4];
#pragma unroll
        for (int mt = 0; mt < 2; mt++)
#pragma unroll
            for (int nt = 0; nt < 8; nt++)
#pragma unroll
                for (int j = 0; j < 4; j++) s[mt][nt][j] = 0.0f;
#pragma unroll
        for (int kk = 0; kk < 4; kk++) {
#pragma unroll
            for (int nt = 0; nt < 8; nt++) {
                unsigned b0 = Kp[(nt * 8 + gid) * KW + kk * 8 + tig];
                unsigned b1 = Kp[(nt * 8 + gid) * KW + kk * 8 + tig + 4];
                mma_f16(s[0][nt], qf[kk][0], b0, b1);
                mma_f16(s[1][nt], qf[kk][1], b0, b1);
            }
        }

        // Online softmax per mt (rows wr+mt*16+gid and +8)
#pragma unroll
        for (int mt = 0; mt < 2; mt++) {
            float mt0 = s[mt][0][0], mt1 = s[mt][0][2];
#pragma unroll
            for (int nt = 0; nt < 8; nt++) {
                mt0 = fmaxf(mt0, fmaxf(s[mt][nt][0], s[mt][nt][1]));
                mt1 = fmaxf(mt1, fmaxf(s[mt][nt][2], s[mt][nt][3]));
            }
            mt0 = fmaxf(mt0, __shfl_xor_sync(0xffffffffu, mt0, 1));
            mt0 = fmaxf(mt0, __shfl_xor_sync(0xffffffffu, mt0, 2));
            mt1 = fmaxf(mt1, __shfl_xor_sync(0xffffffffu, mt1, 1));
            mt1 = fmaxf(mt1, __shfl_xor_sync(0xffffffffu, mt1, 2));

            const float mn0 = fmaxf(mrow[mt][0], mt0);
            const float mn1 = fmaxf(mrow[mt][1], mt1);
            const float al0 = __expf(mrow[mt][0] - mn0);
            const float al1 = __expf(mrow[mt][1] - mn1);
            float ls0 = 0.0f, ls1 = 0.0f;
#pragma unroll
            for (int nt = 0; nt < 8; nt++) {
                s[mt][nt][0] = __expf(s[mt][nt][0] - mn0); ls0 += s[mt][nt][0];
                s[mt][nt][1] = __expf(s[mt][nt][1] - mn0); ls0 += s[mt][nt][1];
                s[mt][nt][2] = __expf(s[mt][nt][2] - mn1); ls1 += s[mt][nt][2];
                s[mt][nt][3] = __expf(s[mt][nt][3] - mn1); ls1 += s[mt][nt][3];
            }
            ls0 += __shfl_xor_sync(0xffffffffu, ls0, 1);
            ls0 += __shfl_xor_sync(0xffffffffu, ls0, 2);
            ls1 += __shfl_xor_sync(0xffffffffu, ls1, 1);
            ls1 += __shfl_xor_sync(0xffffffffu, ls1, 2);
            lrow[mt][0] = lrow[mt][0] * al0 + ls0;
            lrow[mt][1] = lrow[mt][1] * al1 + ls1;
            mrow[mt][0] = mn0; mrow[mt][1] = mn1;
#pragma unroll
            for (int nt = 0; nt < 8; nt++) {
                o[mt][nt][0] *= al0; o[mt][nt][1] *= al0;
                o[mt][nt][2] *= al1; o[mt][nt][3] *= al1;
            }
        }

        // Pack P C-frag -> PV A-frag (f16x2), zero smem traffic
        unsigned ap[4][2][4];
#pragma unroll
        for (int kk = 0; kk < 4; kk++)
#pragma unroll
            for (int mt = 0; mt < 2; mt++) {
                ap[kk][mt][0] = pack_h2(s[mt][2 * kk][0],     s[mt][2 * kk][1]);
                ap[kk][mt][1] = pack_h2(s[mt][2 * kk][2],     s[mt][2 * kk][3]);
                ap[kk][mt][2] = pack_h2(s[mt][2 * kk + 1][0], s[mt][2 * kk + 1][1]);
                ap[kk][mt][3] = pack_h2(s[mt][2 * kk + 1][2], s[mt][2 * kk + 1][3]);
            }

        // O += P @ V   (V transposed in smem: b-frag words contiguous)
#pragma unroll
        for (int kk = 0; kk < 4; kk++) {
#pragma unroll
            for (int nt = 0; nt < 8; nt++) {
                unsigned b0 = Vp[(nt * 8 + gid) * KW + kk * 8 + tig];
                unsigned b1 = Vp[(nt * 8 + gid) * KW + kk * 8 + tig + 4];
                mma_f16(o[0][nt], ap[kk][0], b0, b1);
                mma_f16(o[1][nt], ap[kk][1], b0, b1);
            }
        }
    }

    // Epilogue: normalize and store fp32 A
    float* Ob = O + ((size_t)b * NN + q0) * INNER + h * HD;
#pragma unroll
    for (int mt = 0; mt < 2; mt++) {
        const int r0 = wr + mt * 16 + gid;
        const float i0 = 1.0f / lrow[mt][0], i1 = 1.0f / lrow[mt][1];
#pragma unroll
        for (int nt = 0; nt < 8; nt++) {
            const int c = nt * 8 + tig * 2;
            *(float2*)(Ob + (size_t)r0 * INNER + c) =
                make_float2(o[mt][nt][0] * i0, o[mt][nt][1] * i0);
            *(float2*)(Ob + (size_t)(r0 + 8) * INNER + c) =
                make_float2(o[mt][nt][2] * i1, o[mt][nt][3] * i1);
        }
    }
}

// ---------------------------------------------------------------------------
extern "C" void kernel_launch(void* const* d_in, const int* in_sizes, int n_in,
                              void* d_out, int out_size) {
    const float* x   = (const float*)d_in[0];
    const float* ctx = (const float*)d_in[1];
    const float* Wq  = (const float*)d_in[2];
    const float* Wk  = (const float*)d_in[3];
    const float* Wv  = (const float*)d_in[4];
    const float* W1  = (const float*)d_in[5];
    const float* b1  = (const float*)d_in[6];
    const float* W2  = (const float*)d_in[7];
    const float* b2  = (const float*)d_in[8];
    const float* Wo  = (const float*)d_in[9];
    const float* bo  = (const float*)d_in[10];
    float* out = (float*)d_out;

    float *gctx, *Ap;
    __half *Qh, *Kh, *Vt;
    cudaGetSymbolAddress((void**)&gctx, g_gctx);
    cudaGetSymbolAddress((void**)&Qh, g_Qh);
    cudaGetSymbolAddress((void**)&Kh, g_Kh);
    cudaGetSymbolAddress((void**)&Vt, g_Vt);
    cudaGetSymbolAddress((void**)&Ap, g_A);

    const int flash_smem = (256 + 4 * 64) * KW * (int)sizeof(unsigned);  // 73728 B
    cudaFuncSetAttribute(flash_f16,
                         cudaFuncAttributeMaxDynamicSharedMemorySize, flash_smem);

    // 1) gated context
    gate_kernel<<<BB * MM / 8, 256>>>(ctx, W1, b1, W2, b2, gctx);

    // 2) projections -> f16 (Q pre-scaled by 1/sqrt(D); V transposed)
    mma_gemm<false, true><<<dim3(INNER / 128, BB * NN / 128), 256>>>(
        x, Wq, nullptr, Qh, BB * NN, INNER, QD, 0.125f);
    sgemm_f16<0><<<dim3(INNER / 128, BB * MM / 128), 256>>>(
        gctx, Wk, Kh, BB * MM, INNER, CD);
    sgemm_f16<1><<<dim3(INNER / 128, BB * MM / 128), 256>>>(
        gctx, Wv, Vt, BB * MM, INNER, CD);

    // 3) attention (f16 tensor cores)
    flash_f16<<<dim3(NN / 256, NH, BB), 256, flash_smem>>>(Qh, Kh, Vt, Ap);

    // 4) output projection + bias -> d_out (tf32)
    mma_gemm<true, false><<<dim3(QD / 128, BB * NN / 128), 256>>>(
        Ap, Wo, bo, out, BB * NN, QD, INNER, 1.0f);
}